// round 7
// baseline (speedup 1.0000x reference)
#include <cuda_runtime.h>
#include <math.h>
#include <stdint.h>

#define DIM 1024
#define BB 4
#define SS 2048
#define NH 16
#define HD 64
#define MROWS (BB*SS)   // 8192

// ---------------------------------------------------------------------------
// Scratch (device globals; no allocation allowed)
// ---------------------------------------------------------------------------
__device__ float g_Q[BB*NH*SS*HD];   // [b,h,s,d] projected Q (x 1/8), tf32-rounded
__device__ float g_K[BB*NH*SS*HD];
__device__ float g_V[BB*NH*SS*HD];
__device__ float g_Z[MROWS*DIM];     // attention out, tf32-rounded
__device__ float g_RQ[MROWS*DIM];    // tf32-rounded inputs
__device__ float g_RK[MROWS*DIM];
__device__ float g_RV[MROWS*DIM];
__device__ float g_RW[4][DIM*DIM];   // tf32-rounded weights
__device__ int   g_maskflag;         // zero-init; reset by out_gemm each run

// ---------------------------------------------------------------------------
// Helpers (compute_103-legal)
// ---------------------------------------------------------------------------
__device__ __forceinline__ uint32_t smem_u32(const void* p) {
    uint32_t a;
    asm("{ .reg .u64 t; cvta.to.shared.u64 t, %1; cvt.u32.u64 %0, t; }" : "=r"(a) : "l"(p));
    return a;
}
__device__ __forceinline__ void cp16(uint32_t dst, const void* src) {
    asm volatile("cp.async.cg.shared.global [%0], [%1], 16;" :: "r"(dst), "l"(src));
}
#define CP_COMMIT() asm volatile("cp.async.commit_group;" ::: "memory")

__device__ __forceinline__ float rna_tf32(float x) {
    uint32_t r;
    asm("cvt.rna.tf32.f32 %0, %1;" : "=r"(r) : "f"(x));
    return __uint_as_float(r);
}
__device__ __forceinline__ void mma_tf32(float d[4], const uint32_t a[4], const uint32_t b[2]) {
    asm volatile(
        "mma.sync.aligned.m16n8k8.row.col.f32.tf32.tf32.f32 "
        "{%0,%1,%2,%3}, {%4,%5,%6,%7}, {%8,%9}, {%0,%1,%2,%3};"
        : "+f"(d[0]), "+f"(d[1]), "+f"(d[2]), "+f"(d[3])
        : "r"(a[0]), "r"(a[1]), "r"(a[2]), "r"(a[3]), "r"(b[0]), "r"(b[1]));
}
__device__ __forceinline__ void ldsm_x4(uint32_t r[4], uint32_t addr) {
    asm volatile("ldmatrix.sync.aligned.m8n8.x4.shared.b16 {%0,%1,%2,%3}, [%4];"
                 : "=r"(r[0]), "=r"(r[1]), "=r"(r[2]), "=r"(r[3]) : "r"(addr));
}

// ---------------------------------------------------------------------------
// Merged pre-round (q,k,v,W*) + mask scan. grid (4096,1,8), 256 thr.
// ---------------------------------------------------------------------------
__global__ __launch_bounds__(256)
void round_all(const float* __restrict__ q, const float* __restrict__ k,
               const float* __restrict__ v, const float* __restrict__ Wq,
               const float* __restrict__ Wk, const float* __restrict__ Wv,
               const float* __restrict__ Wd, const float* __restrict__ mask)
{
    const int z = blockIdx.z;
    const int tid = threadIdx.x;
    if (z == 7) {   // mask scan
        const float4* m4 = (const float4*)mask;
        const size_t base = (size_t)blockIdx.x * 1024 + tid;
        bool nz = false;
#pragma unroll
        for (int i = 0; i < 4; i++) {
            float4 vv = m4[base + (size_t)i * 256];
            nz |= (vv.x != 0.f) | (vv.y != 0.f) | (vv.z != 0.f) | (vv.w != 0.f);
        }
        if (__syncthreads_or(nz) && tid == 0) atomicExch(&g_maskflag, 1);
        return;
    }
    const float* src; float* dst; int nblk;
    switch (z) {
        case 0: src = q;  dst = g_RQ;    nblk = 2048; break;
        case 1: src = k;  dst = g_RK;    nblk = 2048; break;
        case 2: src = v;  dst = g_RV;    nblk = 2048; break;
        case 3: src = Wq; dst = g_RW[0]; nblk = 256;  break;
        case 4: src = Wk; dst = g_RW[1]; nblk = 256;  break;
        case 5: src = Wv; dst = g_RW[2]; nblk = 256;  break;
        default: src = Wd; dst = g_RW[3]; nblk = 256; break;
    }
    if (blockIdx.x >= (unsigned)nblk) return;
    const float4* s4 = (const float4*)src;
    float4* d4 = (float4*)dst;
    const size_t base = (size_t)blockIdx.x * 1024 + tid;
    float4 vv[4];
#pragma unroll
    for (int i = 0; i < 4; i++) vv[i] = s4[base + (size_t)i * 256];
#pragma unroll
    for (int i = 0; i < 4; i++) {
        vv[i].x = rna_tf32(vv[i].x); vv[i].y = rna_tf32(vv[i].y);
        vv[i].z = rna_tf32(vv[i].z); vv[i].w = rna_tf32(vv[i].w);
        d4[base + (size_t)i * 256] = vv[i];
    }
}

// ---------------------------------------------------------------------------
// GEMM core: C = scale * (A[M,K] @ W[N,K]^T), K=1024. Operands pre-rounded.
// BM=BN=128, BK=16, 256 threads (8 warps 2x4, warp tile 64x32), 4-stage pipe.
// Fragments via ldmatrix.x4.
// ---------------------------------------------------------------------------
#define PST 20                       // smem row stride (16 + 4 pad), floats
#define STG_F (2 * 128 * PST)        // A+B floats per stage = 5120
#define GEMM_SMEM (4 * STG_F * 4)    // 81920 bytes

template<int LAYOUT, int ROUND>
__device__ __forceinline__
void gemm_core(const float* __restrict__ A, const float* __restrict__ W,
               float* __restrict__ C, float scale, float* sm)
{
    const int tid = threadIdx.x;
    const int lane = tid & 31, wid = tid >> 5;
    const int wr = wid >> 2, wc = wid & 3;       // 2x4 warp grid, warp tile 64x32
    const int r0 = lane >> 2, c0 = lane & 3;
    const int g = lane >> 3, lr = lane & 7;
    const int row0 = blockIdx.x * 128, col0 = blockIdx.y * 128;
    const uint32_t smb = smem_u32(sm);

    // ldsm offsets (floats)
    const int aoff = (wr * 64 + lr + (g & 1) * 8) * PST + (g >> 1) * 4;   // A-style
    const int boff = (wc * 32 + lr + (g >> 1) * 8) * PST + (g & 1) * 4;   // B-style

    float acc[4][4][4];
#pragma unroll
    for (int mt = 0; mt < 4; mt++)
#pragma unroll
        for (int nt = 0; nt < 4; nt++)
#pragma unroll
            for (int j = 0; j < 4; j++) acc[mt][nt][j] = 0.f;

    auto load_stage = [&](int kt, int s) {
        uint32_t a_s = smb + s * (STG_F * 4);
        uint32_t b_s = a_s + 128 * PST * 4;
#pragma unroll
        for (int i = 0; i < 2; i++) {
            int c = tid + 256 * i;               // 0..511
            int row = c >> 2, c4 = c & 3;
            uint32_t so = (uint32_t)(row * PST + c4 * 4) * 4;
            cp16(a_s + so, A + (size_t)(row0 + row) * DIM + kt * 16 + c4 * 4);
            cp16(b_s + so, W + (size_t)(col0 + row) * DIM + kt * 16 + c4 * 4);
        }
    };

    load_stage(0, 0); CP_COMMIT();
    load_stage(1, 1); CP_COMMIT();
    load_stage(2, 2); CP_COMMIT();

    const int NT = DIM / 16;                     // 64
    for (int kt = 0; kt < NT; kt++) {
        asm volatile("cp.async.wait_group 2;" ::: "memory");
        __syncthreads();
        if (kt + 3 < NT) load_stage(kt + 3, (kt + 3) & 3);
        CP_COMMIT();

        const uint32_t a_s = smb + (kt & 3) * (STG_F * 4);
        const uint32_t b_s = a_s + 128 * PST * 4;
#pragma unroll
        for (int ks = 0; ks < 2; ks++) {
            const int kb = ks * 8;
            uint32_t a[4][4];
#pragma unroll
            for (int mt = 0; mt < 4; mt++)
                ldsm_x4(a[mt], a_s + (uint32_t)(aoff + mt * 16 * PST + kb) * 4);
            uint32_t bp[2][4];                   // pair p covers nt=2p, 2p+1
#pragma unroll
            for (int p = 0; p < 2; p++)
                ldsm_x4(bp[p], b_s + (uint32_t)(boff + p * 16 * PST + kb) * 4);
#pragma unroll
            for (int nt = 0; nt < 4; nt++) {
                const uint32_t bfr[2] = { bp[nt >> 1][(nt & 1) * 2],
                                          bp[nt >> 1][(nt & 1) * 2 + 1] };
#pragma unroll
                for (int mt = 0; mt < 4; mt++)
                    mma_tf32(acc[mt][nt], a[mt], bfr);
            }
        }
    }

#pragma unroll
    for (int mt = 0; mt < 4; mt++) {
        const int rA = row0 + wr * 64 + mt * 16 + r0;
#pragma unroll
        for (int rr = 0; rr < 2; rr++) {
            const int r = rA + rr * 8;
#pragma unroll
            for (int nt = 0; nt < 4; nt++) {
                const int col = col0 + wc * 32 + nt * 8 + 2 * c0;
                float v0 = acc[mt][nt][rr * 2 + 0] * scale;
                float v1 = acc[mt][nt][rr * 2 + 1] * scale;
                if (ROUND) { v0 = rna_tf32(v0); v1 = rna_tf32(v1); }
                float2 val = make_float2(v0, v1);
                if (LAYOUT == 0) {
                    const int b = r >> 11, s = r & (SS - 1);
                    const int h = col >> 6, d = col & 63;
                    *(float2*)(C + ((size_t)((b * NH + h) * SS) + s) * HD + d) = val;
                } else {
                    *(float2*)(C + (size_t)r * DIM + col) = val;
                }
            }
        }
    }
}

__global__ __launch_bounds__(256, 2)
void qkv_gemm()
{
    extern __shared__ float sm[];
    const int z = blockIdx.z;
    const float* A = (z == 0) ? g_RQ : (z == 1) ? g_RK : g_RV;
    const float* W = g_RW[z];
    float* C = (z == 0) ? g_Q : (z == 1) ? g_K : g_V;
    gemm_core<0, 1>(A, W, C, (z == 0) ? 0.125f : 1.0f, sm);
}

__global__ __launch_bounds__(256, 2)
void out_gemm(float* __restrict__ C)
{
    extern __shared__ float sm[];
    gemm_core<1, 0>(g_Z, g_RW[3], C, 1.0f, sm);
    if (blockIdx.x == 0 && blockIdx.y == 0 && threadIdx.x == 0)
        g_maskflag = 0;   // for the next graph replay
}

// ---------------------------------------------------------------------------
// mma.sync tf32 flash attention, LDSM fragments for Q/K/P.
// CTA: 256 thr (8 warps), 128 q-rows (16/warp), 64 iters of 32 keys.
// K/V double-buffered via cp.async.
// ---------------------------------------------------------------------------
#define KST 68
#define VST 72
#define KS_F (32 * KST)
#define VS_F (32 * VST)
#define ATTN_SMEM ((2*KS_F + 2*VS_F + 128*KST) * 4)   // 70656 B

__global__ __launch_bounds__(256, 2)
void attn_mma(const float* __restrict__ mask)
{
    extern __shared__ float sm[];
    float* Ks = sm;
    float* Vs = sm + 2 * KS_F;
    float* Ps = sm + 2 * KS_F + 2 * VS_F;
    const uint32_t ks_b = smem_u32(Ks);
    const uint32_t vs_b = smem_u32(Vs);
    const uint32_t ps_b = smem_u32(Ps);

    const int tid = threadIdx.x, lane = tid & 31, w = tid >> 5;
    const int r0 = lane >> 2, c0 = lane & 3;
    const int g = lane >> 3, lr = lane & 7;
    const int q0 = blockIdx.x * 128;
    const int bh = blockIdx.y, b = bh >> 4, h = bh & 15;
    const int use_mask = g_maskflag;

    // ldsm offsets (floats)
    const int pAoff = (w * 16 + lr + (g & 1) * 8) * KST + (g >> 1) * 4;  // A-style
    const int kBoff = (lr + (g >> 1) * 8) * KST + (g & 1) * 4;           // B-style

    const float* Kg0 = g_K + (size_t)bh * SS * HD;
    const float* Vg0 = g_V + (size_t)bh * SS * HD;

    const float* Qg = g_Q + ((size_t)bh * SS + q0) * HD;
#pragma unroll
    for (int i = 0; i < 8; i++) {
        int c = tid + 256 * i;
        int row = c >> 4, c4 = c & 15;
        *(float4*)&Ps[row * KST + c4 * 4] = *(const float4*)(Qg + (size_t)row * HD + c4 * 4);
    }
    __syncthreads();
    uint32_t qf[8][4];
#pragma unroll
    for (int ks = 0; ks < 8; ks++)
        ldsm_x4(qf[ks], ps_b + (uint32_t)(pAoff + ks * 8) * 4);
    __syncthreads();

    float o[8][4];
#pragma unroll
    for (int nt = 0; nt < 8; nt++)
#pragma unroll
        for (int j = 0; j < 4; j++) o[nt][j] = 0.f;
    float m_lo = -INFINITY, m_hi = -INFINITY, l_lo = 0.f, l_hi = 0.f;

    auto load_kv = [&](int t, int s) {
#pragma unroll
        for (int i = 0; i < 2; i++) {
            int c = tid + 256 * i;               // 0..511
            int row = c >> 4, c4 = c & 15;
            cp16(ks_b + (uint32_t)(s * KS_F + row * KST + c4 * 4) * 4,
                 Kg0 + (size_t)(t * 32 + row) * HD + c4 * 4);
            cp16(vs_b + (uint32_t)(s * VS_F + row * VST + c4 * 4) * 4,
                 Vg0 + (size_t)(t * 32 + row) * HD + c4 * 4);
        }
    };

    load_kv(0, 0); CP_COMMIT();

    const int NIT = SS / 32;
    for (int it = 0; it < NIT; it++) {
        if (it + 1 < NIT) load_kv(it + 1, (it + 1) & 1);
        CP_COMMIT();
        asm volatile("cp.async.wait_group 1;" ::: "memory");
        __syncthreads();

        const uint32_t ksb = ks_b + (uint32_t)((it & 1) * KS_F) * 4;
        const float* Vsb = Vs + (it & 1) * VS_F;

        // S = Q @ K^T  (per warp: 16 x 32)
        float s[4][4];
#pragma unroll
        for (int nt = 0; nt < 4; nt++)
#pragma unroll
            for (int j = 0; j < 4; j++) s[nt][j] = 0.f;
#pragma unroll
        for (int ks = 0; ks < 8; ks++) {
            uint32_t kp[2][4];
            ldsm_x4(kp[0], ksb + (uint32_t)(kBoff + ks * 8) * 4);
            ldsm_x4(kp[1], ksb + (uint32_t)(kBoff + 16 * KST + ks * 8) * 4);
#pragma unroll
            for (int nt = 0; nt < 4; nt++) {
                const uint32_t bfr[2] = { kp[nt >> 1][(nt & 1) * 2],
                                          kp[nt >> 1][(nt & 1) * 2 + 1] };
                mma_tf32(s[nt], qf[ks], bfr);
            }
        }

        if (use_mask) {
            const float* Mg = mask + ((size_t)b * SS + (q0 + w * 16 + r0)) * SS + it * 32;
#pragma unroll
            for (int nt = 0; nt < 4; nt++) {
                float2 mlo = *(const float2*)(Mg + nt * 8 + 2 * c0);
                float2 mhi = *(const float2*)(Mg + (size_t)8 * SS + nt * 8 + 2 * c0);
                s[nt][0] += mlo.x; s[nt][1] += mlo.y;
                s[nt][2] += mhi.x; s[nt][3] += mhi.y;
            }
        }

        // online softmax + P store (tf32-rounded)
        {
            float mx_lo = -INFINITY, mx_hi = -INFINITY;
#pragma unroll
            for (int nt = 0; nt < 4; nt++) {
                mx_lo = fmaxf(mx_lo, fmaxf(s[nt][0], s[nt][1]));
                mx_hi = fmaxf(mx_hi, fmaxf(s[nt][2], s[nt][3]));
            }
            mx_lo = fmaxf(mx_lo, __shfl_xor_sync(0xffffffffu, mx_lo, 1));
            mx_lo = fmaxf(mx_lo, __shfl_xor_sync(0xffffffffu, mx_lo, 2));
            mx_hi = fmaxf(mx_hi, __shfl_xor_sync(0xffffffffu, mx_hi, 1));
            mx_hi = fmaxf(mx_hi, __shfl_xor_sync(0xffffffffu, mx_hi, 2));
            const float nm_lo = fmaxf(m_lo, mx_lo);
            const float nm_hi = fmaxf(m_hi, mx_hi);
            const float corr_lo = __expf(m_lo - nm_lo);
            const float corr_hi = __expf(m_hi - nm_hi);
            m_lo = nm_lo; m_hi = nm_hi;

            float sum_lo = 0.f, sum_hi = 0.f;
            float* Pw0 = &Ps[(w * 16 + r0) * KST];
            float* Pw1 = Pw0 + 8 * KST;
#pragma unroll
            for (int nt = 0; nt < 4; nt++) {
                float p0 = __expf(s[nt][0] - nm_lo);
                float p1 = __expf(s[nt][1] - nm_lo);
                float p2 = __expf(s[nt][2] - nm_hi);
                float p3 = __expf(s[nt][3] - nm_hi);
                sum_lo += p0 + p1; sum_hi += p2 + p3;
                *(float2*)(Pw0 + nt * 8 + 2 * c0) = make_float2(rna_tf32(p0), rna_tf32(p1));
                *(float2*)(Pw1 + nt * 8 + 2 * c0) = make_float2(rna_tf32(p2), rna_tf32(p3));
            }
            sum_lo += __shfl_xor_sync(0xffffffffu, sum_lo, 1);
            sum_lo += __shfl_xor_sync(0xffffffffu, sum_lo, 2);
            sum_hi += __shfl_xor_sync(0xffffffffu, sum_hi, 1);
            sum_hi += __shfl_xor_sync(0xffffffffu, sum_hi, 2);
            l_lo = l_lo * corr_lo + sum_lo;
            l_hi = l_hi * corr_hi + sum_hi;
#pragma unroll
            for (int nt = 0; nt < 8; nt++) {
                o[nt][0] *= corr_lo; o[nt][1] *= corr_lo;
                o[nt][2] *= corr_hi; o[nt][3] *= corr_hi;
            }
        }
        __syncwarp();

        // O += P @ V  (per warp: 16 x 64, k=32); P-frags via ldsm, V scalar
#pragma unroll
        for (int kk = 0; kk < 4; kk++) {
            uint32_t aa[4];
            ldsm_x4(aa, ps_b + (uint32_t)(pAoff + kk * 8) * 4);
#pragma unroll
            for (int nt = 0; nt < 8; nt++) {
                uint32_t bb[2];
                bb[0] = __float_as_uint(Vsb[(kk * 8 + c0)     * VST + nt * 8 + r0]);
                bb[1] = __float_as_uint(Vsb[(kk * 8 + c0 + 4) * VST + nt * 8 + r0]);
                mma_tf32(o[nt], aa, bb);
            }
        }
        __syncthreads();
    }

    // epilogue
    const float inv_lo = 1.f / l_lo, inv_hi = 1.f / l_hi;
    const int qlo = q0 + w * 16 + r0;
    float* Zlo = g_Z + ((size_t)b * SS + qlo) * DIM + h * HD;
    float* Zhi = Zlo + (size_t)8 * DIM;
#pragma unroll
    for (int nt = 0; nt < 8; nt++) {
        const int d = nt * 8 + 2 * c0;
        *(float2*)(Zlo + d) = make_float2(rna_tf32(o[nt][0] * inv_lo),
                                          rna_tf32(o[nt][1] * inv_lo));
        *(float2*)(Zhi + d) = make_float2(rna_tf32(o[nt][2] * inv_hi),
                                          rna_tf32(o[nt][3] * inv_hi));
    }
}

// ---------------------------------------------------------------------------
extern "C" void kernel_launch(void* const* d_in, const int* in_sizes, int n_in,
                              void* d_out, int out_size)
{
    const float* q    = (const float*)d_in[0];
    const float* k    = (const float*)d_in[1];
    const float* v    = (const float*)d_in[2];
    const float* mask = (const float*)d_in[3];
    const float* Wq   = (const float*)d_in[4];
    const float* Wk   = (const float*)d_in[5];
    const float* Wv   = (const float*)d_in[6];
    const float* Wd   = (const float*)d_in[7];

    cudaFuncSetAttribute(qkv_gemm, cudaFuncAttributeMaxDynamicSharedMemorySize, GEMM_SMEM);
    cudaFuncSetAttribute(out_gemm, cudaFuncAttributeMaxDynamicSharedMemorySize, GEMM_SMEM);
    cudaFuncSetAttribute(attn_mma, cudaFuncAttributeMaxDynamicSharedMemorySize, ATTN_SMEM);

    // launch 1: pre-round everything + mask scan
    round_all<<<dim3(4096, 1, 8), 256>>>(q, k, v, Wq, Wk, Wv, Wd, mask);

    // launch 2: q/k/v projections
    qkv_gemm<<<dim3(MROWS/128, DIM/128, 3), 256, GEMM_SMEM>>>();

    // launch 3: flash attention
    attn_mma<<<dim3(SS/128, BB*NH), 256, ATTN_SMEM>>>(mask);

    // launch 4: output projection (+ maskflag reset)
    out_gemm<<<dim3(MROWS/128, DIM/128), 256, GEMM_SMEM>>>((float*)d_out);
}

// round 8
// speedup vs baseline: 1.0433x; 1.0433x over previous
#include <cuda_runtime.h>
#include <math.h>
#include <stdint.h>

#define DIM 1024
#define BB 4
#define SS 2048
#define NH 16
#define HD 64
#define MROWS (BB*SS)   // 8192

// ---------------------------------------------------------------------------
// Scratch (device globals; no allocation allowed)
// ---------------------------------------------------------------------------
__device__ float g_Q[BB*NH*SS*HD];   // [b,h,s,d] projected Q (x 1/8), tf32-rounded
__device__ float g_K[BB*NH*SS*HD];   // [b,h,s,d]
__device__ float g_V[BB*NH*SS*HD];   // [b,h,d,s]  (TRANSPOSED)
__device__ float g_Z[MROWS*DIM];     // attention out, tf32-rounded
__device__ float g_RQ[MROWS*DIM];    // tf32-rounded inputs
__device__ float g_RK[MROWS*DIM];
__device__ float g_RV[MROWS*DIM];
__device__ float g_RW[4][DIM*DIM];   // tf32-rounded weights
__device__ int   g_maskflag;         // zero-init; reset by out_gemm each run

// ---------------------------------------------------------------------------
// Helpers (compute_103-legal)
// ---------------------------------------------------------------------------
__device__ __forceinline__ uint32_t smem_u32(const void* p) {
    uint32_t a;
    asm("{ .reg .u64 t; cvta.to.shared.u64 t, %1; cvt.u32.u64 %0, t; }" : "=r"(a) : "l"(p));
    return a;
}
__device__ __forceinline__ void cp16(uint32_t dst, const void* src) {
    asm volatile("cp.async.cg.shared.global [%0], [%1], 16;" :: "r"(dst), "l"(src));
}
#define CP_COMMIT() asm volatile("cp.async.commit_group;" ::: "memory")

__device__ __forceinline__ float rna_tf32(float x) {
    uint32_t r;
    asm("cvt.rna.tf32.f32 %0, %1;" : "=r"(r) : "f"(x));
    return __uint_as_float(r);
}
__device__ __forceinline__ void mma_tf32(float d[4], const uint32_t a[4], const uint32_t b[2]) {
    asm volatile(
        "mma.sync.aligned.m16n8k8.row.col.f32.tf32.tf32.f32 "
        "{%0,%1,%2,%3}, {%4,%5,%6,%7}, {%8,%9}, {%0,%1,%2,%3};"
        : "+f"(d[0]), "+f"(d[1]), "+f"(d[2]), "+f"(d[3])
        : "r"(a[0]), "r"(a[1]), "r"(a[2]), "r"(a[3]), "r"(b[0]), "r"(b[1]));
}
__device__ __forceinline__ void ldsm_x4(uint32_t r[4], uint32_t addr) {
    asm volatile("ldmatrix.sync.aligned.m8n8.x4.shared.b16 {%0,%1,%2,%3}, [%4];"
                 : "=r"(r[0]), "=r"(r[1]), "=r"(r[2]), "=r"(r[3]) : "r"(addr));
}

// ---------------------------------------------------------------------------
// Merged pre-round (q,k,v,W*) + mask scan. grid (4096,1,8), 256 thr.
// ---------------------------------------------------------------------------
__global__ __launch_bounds__(256)
void round_all(const float* __restrict__ q, const float* __restrict__ k,
               const float* __restrict__ v, const float* __restrict__ Wq,
               const float* __restrict__ Wk, const float* __restrict__ Wv,
               const float* __restrict__ Wd, const float* __restrict__ mask)
{
    const int z = blockIdx.z;
    const int tid = threadIdx.x;
    if (z == 7) {   // mask scan
        const float4* m4 = (const float4*)mask;
        const size_t base = (size_t)blockIdx.x * 1024 + tid;
        bool nz = false;
#pragma unroll
        for (int i = 0; i < 4; i++) {
            float4 vv = m4[base + (size_t)i * 256];
            nz |= (vv.x != 0.f) | (vv.y != 0.f) | (vv.z != 0.f) | (vv.w != 0.f);
        }
        if (__syncthreads_or(nz) && tid == 0) atomicExch(&g_maskflag, 1);
        return;
    }
    const float* src; float* dst; int nblk;
    switch (z) {
        case 0: src = q;  dst = g_RQ;    nblk = 2048; break;
        case 1: src = k;  dst = g_RK;    nblk = 2048; break;
        case 2: src = v;  dst = g_RV;    nblk = 2048; break;
        case 3: src = Wq; dst = g_RW[0]; nblk = 256;  break;
        case 4: src = Wk; dst = g_RW[1]; nblk = 256;  break;
        case 5: src = Wv; dst = g_RW[2]; nblk = 256;  break;
        default: src = Wd; dst = g_RW[3]; nblk = 256; break;
    }
    if (blockIdx.x >= (unsigned)nblk) return;
    const float4* s4 = (const float4*)src;
    float4* d4 = (float4*)dst;
    const size_t base = (size_t)blockIdx.x * 1024 + tid;
    float4 vv[4];
#pragma unroll
    for (int i = 0; i < 4; i++) vv[i] = s4[base + (size_t)i * 256];
#pragma unroll
    for (int i = 0; i < 4; i++) {
        vv[i].x = rna_tf32(vv[i].x); vv[i].y = rna_tf32(vv[i].y);
        vv[i].z = rna_tf32(vv[i].z); vv[i].w = rna_tf32(vv[i].w);
        d4[base + (size_t)i * 256] = vv[i];
    }
}

// ---------------------------------------------------------------------------
// GEMM core (round-6 config): BM=BN=128, BK=16, 128 threads (2x2 warps,
// warp tile 64x64), 4-stage cp.async pipe, fragments via ldmatrix.x4.
// LAYOUT 0: head layout [b,h,s,d];  LAYOUT 1: row-major;  LAYOUT 2: [b,h,d,s].
// ---------------------------------------------------------------------------
#define PST 20                       // smem row stride (16 + 4 pad), floats
#define STG_F (2 * 128 * PST)        // A+B floats per stage = 5120
#define GEMM_SMEM (4 * STG_F * 4)    // 81920 bytes

template<int LAYOUT, int ROUND>
__device__ __forceinline__
void gemm_core(const float* __restrict__ A, const float* __restrict__ W,
               float* __restrict__ C, float scale, float* sm)
{
    const int tid = threadIdx.x;
    const int lane = tid & 31, wid = tid >> 5;
    const int wr = wid >> 1, wc = wid & 1;       // 2x2 warp grid, warp tile 64x64
    const int r0 = lane >> 2, c0 = lane & 3;
    const int g = lane >> 3, lr = lane & 7;
    const int row0 = blockIdx.x * 128, col0 = blockIdx.y * 128;
    const uint32_t smb = smem_u32(sm);

    const int aoff = (wr * 64 + lr + (g & 1) * 8) * PST + (g >> 1) * 4;   // A-style
    const int boff = (wc * 64 + lr + (g >> 1) * 8) * PST + (g & 1) * 4;   // B-style

    float acc[4][8][4];
#pragma unroll
    for (int mt = 0; mt < 4; mt++)
#pragma unroll
        for (int nt = 0; nt < 8; nt++)
#pragma unroll
            for (int j = 0; j < 4; j++) acc[mt][nt][j] = 0.f;

    auto load_stage = [&](int kt, int s) {
        uint32_t a_s = smb + s * (STG_F * 4);
        uint32_t b_s = a_s + 128 * PST * 4;
#pragma unroll
        for (int i = 0; i < 4; i++) {
            int c = tid + 128 * i;               // 0..511
            int row = c >> 2, c4 = c & 3;
            uint32_t so = (uint32_t)(row * PST + c4 * 4) * 4;
            cp16(a_s + so, A + (size_t)(row0 + row) * DIM + kt * 16 + c4 * 4);
            cp16(b_s + so, W + (size_t)(col0 + row) * DIM + kt * 16 + c4 * 4);
        }
    };

    load_stage(0, 0); CP_COMMIT();
    load_stage(1, 1); CP_COMMIT();
    load_stage(2, 2); CP_COMMIT();

    const int NT = DIM / 16;                     // 64
    for (int kt = 0; kt < NT; kt++) {
        asm volatile("cp.async.wait_group 2;" ::: "memory");
        __syncthreads();
        if (kt + 3 < NT) load_stage(kt + 3, (kt + 3) & 3);
        CP_COMMIT();

        const uint32_t a_s = smb + (kt & 3) * (STG_F * 4);
        const uint32_t b_s = a_s + 128 * PST * 4;
#pragma unroll
        for (int ks = 0; ks < 2; ks++) {
            const int kb = ks * 8;
            uint32_t a[4][4];
#pragma unroll
            for (int mt = 0; mt < 4; mt++)
                ldsm_x4(a[mt], a_s + (uint32_t)(aoff + mt * 16 * PST + kb) * 4);
            uint32_t bp[4][4];                   // pair p covers nt=2p, 2p+1
#pragma unroll
            for (int p = 0; p < 4; p++)
                ldsm_x4(bp[p], b_s + (uint32_t)(boff + p * 16 * PST + kb) * 4);
#pragma unroll
            for (int nt = 0; nt < 8; nt++) {
                const uint32_t bfr[2] = { bp[nt >> 1][(nt & 1) * 2],
                                          bp[nt >> 1][(nt & 1) * 2 + 1] };
#pragma unroll
                for (int mt = 0; mt < 4; mt++)
                    mma_tf32(acc[mt][nt], a[mt], bfr);
            }
        }
    }

#pragma unroll
    for (int mt = 0; mt < 4; mt++) {
        const int rA = row0 + wr * 64 + mt * 16 + r0;
#pragma unroll
        for (int rr = 0; rr < 2; rr++) {
            const int r = rA + rr * 8;
#pragma unroll
            for (int nt = 0; nt < 8; nt++) {
                const int col = col0 + wc * 64 + nt * 8 + 2 * c0;
                float v0 = acc[mt][nt][rr * 2 + 0] * scale;
                float v1 = acc[mt][nt][rr * 2 + 1] * scale;
                if (ROUND) { v0 = rna_tf32(v0); v1 = rna_tf32(v1); }
                if (LAYOUT == 0) {
                    const int b = r >> 11, s = r & (SS - 1);
                    const int h = col >> 6, d = col & 63;
                    *(float2*)(C + ((size_t)((b * NH + h) * SS) + s) * HD + d) =
                        make_float2(v0, v1);
                } else if (LAYOUT == 1) {
                    *(float2*)(C + (size_t)r * DIM + col) = make_float2(v0, v1);
                } else {   // LAYOUT 2: transposed [b,h,d,s]
                    const int b = r >> 11, s = r & (SS - 1);
                    const int h = col >> 6, d = col & 63;
                    float* base = C + ((size_t)(b * NH + h) * HD + d) * SS + s;
                    base[0]  = v0;
                    base[SS] = v1;
                }
            }
        }
    }
}

__global__ __launch_bounds__(128, 2)
void qkv_gemm()
{
    extern __shared__ float sm[];
    const int z = blockIdx.z;
    if (z == 0)      gemm_core<0, 1>(g_RQ, g_RW[0], g_Q, 0.125f, sm);
    else if (z == 1) gemm_core<0, 1>(g_RK, g_RW[1], g_K, 1.0f, sm);
    else             gemm_core<2, 1>(g_RV, g_RW[2], g_V, 1.0f, sm);
}

__global__ __launch_bounds__(128, 2)
void out_gemm(float* __restrict__ C)
{
    extern __shared__ float sm[];
    gemm_core<1, 0>(g_Z, g_RW[3], C, 1.0f, sm);
    if (blockIdx.x == 0 && blockIdx.y == 0 && threadIdx.x == 0)
        g_maskflag = 0;   // for the next graph replay
}

// ---------------------------------------------------------------------------
// mma.sync tf32 flash attention (round-6 shape) with V transposed in smem:
// CTA: 128 thr (4 warps), 128 q-rows (32/warp, mt=2), 64 iters of 32 keys.
// K tiles [32 keys][64 d]; V tiles [64 d][32 keys] -> PV B-frags via ldmatrix.
// ---------------------------------------------------------------------------
#define KST 68
#define VTST 36
#define KS_F (32 * KST)              // 2176 floats per K stage
#define VS_F (64 * VTST)             // 2304 floats per V stage
#define ATTN_SMEM ((2*KS_F + 2*VS_F + 128*KST) * 4)   // 70656 B

__global__ __launch_bounds__(128, 2)
void attn_mma(const float* __restrict__ mask)
{
    extern __shared__ float sm[];
    float* Ks = sm;
    float* Vs = sm + 2 * KS_F;
    float* Ps = sm + 2 * KS_F + 2 * VS_F;
    const uint32_t ks_b = smem_u32(Ks);
    const uint32_t vs_b = smem_u32(Vs);
    const uint32_t ps_b = smem_u32(Ps);

    const int tid = threadIdx.x, lane = tid & 31, w = tid >> 5;
    const int r0 = lane >> 2, c0 = lane & 3;
    const int g = lane >> 3, lr = lane & 7;
    const int q0 = blockIdx.x * 128;
    const int bh = blockIdx.y, b = bh >> 4, h = bh & 15;
    const int use_mask = g_maskflag;

    // ldsm offsets (floats)
    const int pAoff = (w * 32 + lr + (g & 1) * 8) * KST + (g >> 1) * 4;  // A-style, Q/P
    const int kBoff = (lr + (g >> 1) * 8) * KST + (g & 1) * 4;           // B-style, K
    const int vBoff = (lr + (g >> 1) * 8) * VTST + (g & 1) * 4;          // B-style, Vt

    const float* Kg0 = g_K + (size_t)bh * SS * HD;
    const float* Vg0 = g_V + (size_t)bh * HD * SS;   // transposed [d][s]

    const float* Qg = g_Q + ((size_t)bh * SS + q0) * HD;
#pragma unroll
    for (int i = 0; i < 16; i++) {
        int c = tid + 128 * i;
        int row = c >> 4, c4 = c & 15;
        *(float4*)&Ps[row * KST + c4 * 4] = *(const float4*)(Qg + (size_t)row * HD + c4 * 4);
    }
    __syncthreads();
    uint32_t qf[2][8][4];
#pragma unroll
    for (int mt = 0; mt < 2; mt++)
#pragma unroll
        for (int ks = 0; ks < 8; ks++)
            ldsm_x4(qf[mt][ks], ps_b + (uint32_t)(pAoff + mt * 16 * KST + ks * 8) * 4);
    __syncthreads();

    float o[2][8][4];
#pragma unroll
    for (int mt = 0; mt < 2; mt++)
#pragma unroll
        for (int nt = 0; nt < 8; nt++)
#pragma unroll
            for (int j = 0; j < 4; j++) o[mt][nt][j] = 0.f;
    float mrow[2][2], lrow[2][2];
#pragma unroll
    for (int mt = 0; mt < 2; mt++) { mrow[mt][0] = mrow[mt][1] = -INFINITY;
                                     lrow[mt][0] = lrow[mt][1] = 0.f; }

    // K: 32 rows x 64 floats (16 cp16/row); V: 64 rows x 32 floats (8 cp16/row)
    auto load_kv = [&](int t, int s) {
#pragma unroll
        for (int i = 0; i < 4; i++) {
            int c = tid + 128 * i;               // 0..511
            int kr = c >> 4, kc = c & 15;
            cp16(ks_b + (uint32_t)(s * KS_F + kr * KST + kc * 4) * 4,
                 Kg0 + (size_t)(t * 32 + kr) * HD + kc * 4);
            int vr = c >> 3, vc = c & 7;
            cp16(vs_b + (uint32_t)(s * VS_F + vr * VTST + vc * 4) * 4,
                 Vg0 + (size_t)vr * SS + t * 32 + vc * 4);
        }
    };

    load_kv(0, 0); CP_COMMIT();

    const int NIT = SS / 32;
    for (int it = 0; it < NIT; it++) {
        if (it + 1 < NIT) load_kv(it + 1, (it + 1) & 1);
        CP_COMMIT();
        asm volatile("cp.async.wait_group 1;" ::: "memory");
        __syncthreads();

        const uint32_t ksb = ks_b + (uint32_t)((it & 1) * KS_F) * 4;
        const uint32_t vsb = vs_b + (uint32_t)((it & 1) * VS_F) * 4;

        // S = Q @ K^T  (per warp: 32 x 32)
        float s[2][4][4];
#pragma unroll
        for (int mt = 0; mt < 2; mt++)
#pragma unroll
            for (int nt = 0; nt < 4; nt++)
#pragma unroll
                for (int j = 0; j < 4; j++) s[mt][nt][j] = 0.f;
#pragma unroll
        for (int ks = 0; ks < 8; ks++) {
            uint32_t kp[2][4];                   // pair p covers nt=2p, 2p+1
            ldsm_x4(kp[0], ksb + (uint32_t)(kBoff + ks * 8) * 4);
            ldsm_x4(kp[1], ksb + (uint32_t)(kBoff + 16 * KST + ks * 8) * 4);
#pragma unroll
            for (int nt = 0; nt < 4; nt++) {
                const uint32_t bfr[2] = { kp[nt >> 1][(nt & 1) * 2],
                                          kp[nt >> 1][(nt & 1) * 2 + 1] };
                mma_tf32(s[0][nt], qf[0][ks], bfr);
                mma_tf32(s[1][nt], qf[1][ks], bfr);
            }
        }

        if (use_mask) {
#pragma unroll
            for (int mt = 0; mt < 2; mt++) {
                const float* Mg = mask + ((size_t)b * SS + (q0 + w * 32 + mt * 16 + r0)) * SS
                                       + it * 32;
#pragma unroll
                for (int nt = 0; nt < 4; nt++) {
                    float2 mlo = *(const float2*)(Mg + nt * 8 + 2 * c0);
                    float2 mhi = *(const float2*)(Mg + (size_t)8 * SS + nt * 8 + 2 * c0);
                    s[mt][nt][0] += mlo.x; s[mt][nt][1] += mlo.y;
                    s[mt][nt][2] += mhi.x; s[mt][nt][3] += mhi.y;
                }
            }
        }

        // online softmax + P store (tf32-rounded)
#pragma unroll
        for (int mt = 0; mt < 2; mt++) {
            float mx_lo = -INFINITY, mx_hi = -INFINITY;
#pragma unroll
            for (int nt = 0; nt < 4; nt++) {
                mx_lo = fmaxf(mx_lo, fmaxf(s[mt][nt][0], s[mt][nt][1]));
                mx_hi = fmaxf(mx_hi, fmaxf(s[mt][nt][2], s[mt][nt][3]));
            }
            mx_lo = fmaxf(mx_lo, __shfl_xor_sync(0xffffffffu, mx_lo, 1));
            mx_lo = fmaxf(mx_lo, __shfl_xor_sync(0xffffffffu, mx_lo, 2));
            mx_hi = fmaxf(mx_hi, __shfl_xor_sync(0xffffffffu, mx_hi, 1));
            mx_hi = fmaxf(mx_hi, __shfl_xor_sync(0xffffffffu, mx_hi, 2));
            const float nm_lo = fmaxf(mrow[mt][0], mx_lo);
            const float nm_hi = fmaxf(mrow[mt][1], mx_hi);
            const float corr_lo = __expf(mrow[mt][0] - nm_lo);
            const float corr_hi = __expf(mrow[mt][1] - nm_hi);
            mrow[mt][0] = nm_lo; mrow[mt][1] = nm_hi;

            float sum_lo = 0.f, sum_hi = 0.f;
            float* Pw0 = &Ps[(w * 32 + mt * 16 + r0) * KST];
            float* Pw1 = Pw0 + 8 * KST;
#pragma unroll
            for (int nt = 0; nt < 4; nt++) {
                float p0 = __expf(s[mt][nt][0] - nm_lo);
                float p1 = __expf(s[mt][nt][1] - nm_lo);
                float p2 = __expf(s[mt][nt][2] - nm_hi);
                float p3 = __expf(s[mt][nt][3] - nm_hi);
                sum_lo += p0 + p1; sum_hi += p2 + p3;
                *(float2*)(Pw0 + nt * 8 + 2 * c0) = make_float2(rna_tf32(p0), rna_tf32(p1));
                *(float2*)(Pw1 + nt * 8 + 2 * c0) = make_float2(rna_tf32(p2), rna_tf32(p3));
            }
            sum_lo += __shfl_xor_sync(0xffffffffu, sum_lo, 1);
            sum_lo += __shfl_xor_sync(0xffffffffu, sum_lo, 2);
            sum_hi += __shfl_xor_sync(0xffffffffu, sum_hi, 1);
            sum_hi += __shfl_xor_sync(0xffffffffu, sum_hi, 2);
            lrow[mt][0] = lrow[mt][0] * corr_lo + sum_lo;
            lrow[mt][1] = lrow[mt][1] * corr_hi + sum_hi;
#pragma unroll
            for (int nt = 0; nt < 8; nt++) {
                o[mt][nt][0] *= corr_lo; o[mt][nt][1] *= corr_lo;
                o[mt][nt][2] *= corr_hi; o[mt][nt][3] *= corr_hi;
            }
        }
        __syncwarp();

        // O += P @ V  (per warp: 32 x 64, k=32); P A-frags + Vt B-frags via ldsm
#pragma unroll
        for (int kk = 0; kk < 4; kk++) {
            uint32_t aa[2][4];
            ldsm_x4(aa[0], ps_b + (uint32_t)(pAoff + kk * 8) * 4);
            ldsm_x4(aa[1], ps_b + (uint32_t)(pAoff + 16 * KST + kk * 8) * 4);
#pragma unroll
            for (int p = 0; p < 4; p++) {        // d-pairs: p covers nt=2p,2p+1
                uint32_t vp[4];
                ldsm_x4(vp, vsb + (uint32_t)(vBoff + p * 16 * VTST + kk * 8) * 4);
#pragma unroll
                for (int half = 0; half < 2; half++) {
                    const int nt = 2 * p + half;
                    const uint32_t bfr[2] = { vp[half * 2], vp[half * 2 + 1] };
                    mma_tf32(o[0][nt], aa[0], bfr);
                    mma_tf32(o[1][nt], aa[1], bfr);
                }
            }
        }
        __syncthreads();
    }

    // epilogue: normalize, round, write Z[b*SS+q][h*HD+d]
#pragma unroll
    for (int mt = 0; mt < 2; mt++) {
        const float inv_lo = 1.f / lrow[mt][0], inv_hi = 1.f / lrow[mt][1];
        const int qlo = q0 + w * 32 + mt * 16 + r0;
        float* Zlo = g_Z + ((size_t)b * SS + qlo) * DIM + h * HD;
        float* Zhi = Zlo + (size_t)8 * DIM;
#pragma unroll
        for (int nt = 0; nt < 8; nt++) {
            const int d = nt * 8 + 2 * c0;
            *(float2*)(Zlo + d) = make_float2(rna_tf32(o[mt][nt][0] * inv_lo),
                                              rna_tf32(o[mt][nt][1] * inv_lo));
            *(float2*)(Zhi + d) = make_float2(rna_tf32(o[mt][nt][2] * inv_hi),
                                              rna_tf32(o[mt][nt][3] * inv_hi));
        }
    }
}

// ---------------------------------------------------------------------------
extern "C" void kernel_launch(void* const* d_in, const int* in_sizes, int n_in,
                              void* d_out, int out_size)
{
    const float* q    = (const float*)d_in[0];
    const float* k    = (const float*)d_in[1];
    const float* v    = (const float*)d_in[2];
    const float* mask = (const float*)d_in[3];
    const float* Wq   = (const float*)d_in[4];
    const float* Wk   = (const float*)d_in[5];
    const float* Wv   = (const float*)d_in[6];
    const float* Wd   = (const float*)d_in[7];

    cudaFuncSetAttribute(qkv_gemm, cudaFuncAttributeMaxDynamicSharedMemorySize, GEMM_SMEM);
    cudaFuncSetAttribute(out_gemm, cudaFuncAttributeMaxDynamicSharedMemorySize, GEMM_SMEM);
    cudaFuncSetAttribute(attn_mma, cudaFuncAttributeMaxDynamicSharedMemorySize, ATTN_SMEM);

    // launch 1: pre-round everything + mask scan
    round_all<<<dim3(4096, 1, 8), 256>>>(q, k, v, Wq, Wk, Wv, Wd, mask);

    // launch 2: q/k/v projections (V written transposed)
    qkv_gemm<<<dim3(MROWS/128, DIM/128, 3), 128, GEMM_SMEM>>>();

    // launch 3: flash attention
    attn_mma<<<dim3(SS/128, BB*NH), 128, ATTN_SMEM>>>(mask);

    // launch 4: output projection (+ maskflag reset)
    out_gemm<<<dim3(MROWS/128, DIM/128), 128, GEMM_SMEM>>>((float*)d_out);
}

// round 9
// speedup vs baseline: 1.8773x; 1.7994x over previous
#include <cuda_runtime.h>
#include <cuda_fp16.h>
#include <math.h>
#include <stdint.h>

#define DIM 1024
#define BB 4
#define SS 2048
#define NH 16
#define HD 64
#define MROWS (BB*SS)   // 8192

// ---------------------------------------------------------------------------
// Scratch (device globals; no allocation allowed) — fp16 operands everywhere
// ---------------------------------------------------------------------------
__device__ __half g_Q[BB*NH*SS*HD];   // [b,h,s,d] projected Q (x 1/8)
__device__ __half g_K[BB*NH*SS*HD];   // [b,h,s,d]
__device__ __half g_V[BB*NH*SS*HD];   // [b,h,s,d]
__device__ __half g_Z[MROWS*DIM];     // attention out
__device__ __half g_RQ[MROWS*DIM];    // fp16 inputs
__device__ __half g_RK[MROWS*DIM];
__device__ __half g_RV[MROWS*DIM];
__device__ __half g_RW[4][DIM*DIM];   // fp16 weights
__device__ int    g_maskflag;         // zero-init; reset by out_gemm each run

// ---------------------------------------------------------------------------
// Helpers (compute_103-legal, sm_80-era PTX)
// ---------------------------------------------------------------------------
__device__ __forceinline__ uint32_t smem_u32(const void* p) {
    uint32_t a;
    asm("{ .reg .u64 t; cvta.to.shared.u64 t, %1; cvt.u32.u64 %0, t; }" : "=r"(a) : "l"(p));
    return a;
}
__device__ __forceinline__ void cp16(uint32_t dst, const void* src) {
    asm volatile("cp.async.cg.shared.global [%0], [%1], 16;" :: "r"(dst), "l"(src));
}
#define CP_COMMIT() asm volatile("cp.async.commit_group;" ::: "memory")

// fp16 mma m16n8k16, f32 accumulate
__device__ __forceinline__ void mma_f16(float d[4], const uint32_t a[4], const uint32_t b[2]) {
    asm volatile(
        "mma.sync.aligned.m16n8k16.row.col.f32.f16.f16.f32 "
        "{%0,%1,%2,%3}, {%4,%5,%6,%7}, {%8,%9}, {%0,%1,%2,%3};"
        : "+f"(d[0]), "+f"(d[1]), "+f"(d[2]), "+f"(d[3])
        : "r"(a[0]), "r"(a[1]), "r"(a[2]), "r"(a[3]), "r"(b[0]), "r"(b[1]));
}
__device__ __forceinline__ void ldsm_x4(uint32_t r[4], uint32_t addr) {
    asm volatile("ldmatrix.sync.aligned.m8n8.x4.shared.b16 {%0,%1,%2,%3}, [%4];"
                 : "=r"(r[0]), "=r"(r[1]), "=r"(r[2]), "=r"(r[3]) : "r"(addr));
}
__device__ __forceinline__ void ldsm_x4_t(uint32_t r[4], uint32_t addr) {
    asm volatile("ldmatrix.sync.aligned.m8n8.x4.trans.shared.b16 {%0,%1,%2,%3}, [%4];"
                 : "=r"(r[0]), "=r"(r[1]), "=r"(r[2]), "=r"(r[3]) : "r"(addr));
}

// ---------------------------------------------------------------------------
// Merged f32->fp16 convert (q,k,v,W*) + mask scan. grid (2048,1,8), 256 thr.
// ---------------------------------------------------------------------------
__global__ __launch_bounds__(256)
void round_all(const float* __restrict__ q, const float* __restrict__ k,
               const float* __restrict__ v, const float* __restrict__ Wq,
               const float* __restrict__ Wk, const float* __restrict__ Wv,
               const float* __restrict__ Wd, const float* __restrict__ mask)
{
    const int z = blockIdx.z;
    const int tid = threadIdx.x;
    if (z == 7) {   // mask scan: 2048 blocks x 256 thr x 8 float4
        const float4* m4 = (const float4*)mask;
        const size_t base = (size_t)blockIdx.x * 2048 + tid;
        bool nz = false;
#pragma unroll
        for (int i = 0; i < 8; i++) {
            float4 vv = m4[base + (size_t)i * 256];
            nz |= (vv.x != 0.f) | (vv.y != 0.f) | (vv.z != 0.f) | (vv.w != 0.f);
        }
        if (__syncthreads_or(nz) && tid == 0) atomicExch(&g_maskflag, 1);
        return;
    }
    const float* src; __half* dst; int nblk;
    switch (z) {
        case 0: src = q;  dst = g_RQ;    nblk = 2048; break;
        case 1: src = k;  dst = g_RK;    nblk = 2048; break;
        case 2: src = v;  dst = g_RV;    nblk = 2048; break;
        case 3: src = Wq; dst = g_RW[0]; nblk = 256;  break;
        case 4: src = Wk; dst = g_RW[1]; nblk = 256;  break;
        case 5: src = Wv; dst = g_RW[2]; nblk = 256;  break;
        default: src = Wd; dst = g_RW[3]; nblk = 256; break;
    }
    if (blockIdx.x >= (unsigned)nblk) return;
    const float4* s4 = (const float4*)src;
    __half2* d2 = (__half2*)dst;                 // float4 index f -> half2 pair 2f, 2f+1
    const size_t base = (size_t)blockIdx.x * 1024 + tid;
#pragma unroll
    for (int i = 0; i < 4; i++) {
        const size_t f = base + (size_t)i * 256;
        float4 vv = s4[f];
        d2[2 * f]     = __float22half2_rn(make_float2(vv.x, vv.y));
        d2[2 * f + 1] = __float22half2_rn(make_float2(vv.z, vv.w));
    }
}

// ---------------------------------------------------------------------------
// fp16 GEMM core: C = scale * (A[M,K] @ W[N,K]^T), K=1024.
// BM=BN=128, BK=32 halves, 128 thr (2x2 warps, warp tile 64x64), 4-stage pipe.
// LAYOUT 0: head layout [b,h,s,d] (half out);  LAYOUT 1: row-major f32 out.
// ---------------------------------------------------------------------------
#define PSTH 40                       // smem row stride in halves (32 + 8)
#define STG_H (2 * 128 * PSTH)        // A+B halves per stage = 10240
#define STG_B (STG_H * 2)             // 20480 bytes
#define GEMM_SMEM (4 * STG_B)         // 81920 bytes

template<int LAYOUT>
__device__ __forceinline__
void gemm_core(const __half* __restrict__ A, const __half* __restrict__ W,
               void* __restrict__ Cv, float scale, char* smc)
{
    const int tid = threadIdx.x;
    const int lane = tid & 31, wid = tid >> 5;
    const int wr = wid >> 1, wc = wid & 1;       // 2x2 warp grid, warp tile 64x64
    const int r0 = lane >> 2, c0 = lane & 3;
    const int g = lane >> 3, lr = lane & 7;
    const int row0 = blockIdx.x * 128, col0 = blockIdx.y * 128;
    const uint32_t smb = smem_u32(smc);

    // ldsm offsets (halves)
    const int aoff = (wr * 64 + lr + (g & 1) * 8) * PSTH + (g >> 1) * 8;   // A-style
    const int boff = (wc * 64 + lr + (g >> 1) * 8) * PSTH + (g & 1) * 8;   // B-style

    float acc[4][8][4];
#pragma unroll
    for (int mt = 0; mt < 4; mt++)
#pragma unroll
        for (int nt = 0; nt < 8; nt++)
#pragma unroll
            for (int j = 0; j < 4; j++) acc[mt][nt][j] = 0.f;

    auto load_stage = [&](int kt, int s) {
        uint32_t a_s = smb + s * STG_B;
        uint32_t b_s = a_s + 128 * PSTH * 2;
#pragma unroll
        for (int i = 0; i < 4; i++) {
            int c = tid + 128 * i;               // 0..511
            int row = c >> 2, c4 = c & 3;        // 4 x 16B chunks per 64B row
            uint32_t so = (uint32_t)(row * PSTH + c4 * 8) * 2;
            cp16(a_s + so, A + (size_t)(row0 + row) * DIM + kt * 32 + c4 * 8);
            cp16(b_s + so, W + (size_t)(col0 + row) * DIM + kt * 32 + c4 * 8);
        }
    };

    load_stage(0, 0); CP_COMMIT();
    load_stage(1, 1); CP_COMMIT();
    load_stage(2, 2); CP_COMMIT();

    const int NT = DIM / 32;                     // 32
    for (int kt = 0; kt < NT; kt++) {
        asm volatile("cp.async.wait_group 2;" ::: "memory");
        __syncthreads();
        if (kt + 3 < NT) load_stage(kt + 3, (kt + 3) & 3);
        CP_COMMIT();

        const uint32_t a_s = smb + (kt & 3) * STG_B;
        const uint32_t b_s = a_s + 128 * PSTH * 2;
#pragma unroll
        for (int ks = 0; ks < 2; ks++) {         // two k16 chunks
            const int kb = ks * 16;
            uint32_t a[4][4];
#pragma unroll
            for (int mt = 0; mt < 4; mt++)
                ldsm_x4(a[mt], a_s + (uint32_t)(aoff + mt * 16 * PSTH + kb) * 2);
            uint32_t bp[4][4];                   // pair p covers nt=2p, 2p+1
#pragma unroll
            for (int p = 0; p < 4; p++)
                ldsm_x4(bp[p], b_s + (uint32_t)(boff + p * 16 * PSTH + kb) * 2);
#pragma unroll
            for (int nt = 0; nt < 8; nt++) {
                const uint32_t bfr[2] = { bp[nt >> 1][(nt & 1) * 2],
                                          bp[nt >> 1][(nt & 1) * 2 + 1] };
#pragma unroll
                for (int mt = 0; mt < 4; mt++)
                    mma_f16(acc[mt][nt], a[mt], bfr);
            }
        }
    }

#pragma unroll
    for (int mt = 0; mt < 4; mt++) {
        const int rA = row0 + wr * 64 + mt * 16 + r0;
#pragma unroll
        for (int rr = 0; rr < 2; rr++) {
            const int r = rA + rr * 8;
#pragma unroll
            for (int nt = 0; nt < 8; nt++) {
                const int col = col0 + wc * 64 + nt * 8 + 2 * c0;
                float v0 = acc[mt][nt][rr * 2 + 0] * scale;
                float v1 = acc[mt][nt][rr * 2 + 1] * scale;
                if (LAYOUT == 0) {
                    const int b = r >> 11, s = r & (SS - 1);
                    const int h = col >> 6, d = col & 63;
                    __half* C = (__half*)Cv;
                    *(__half2*)(C + ((size_t)((b * NH + h) * SS) + s) * HD + d) =
                        __float22half2_rn(make_float2(v0, v1));
                } else {
                    float* C = (float*)Cv;
                    *(float2*)(C + (size_t)r * DIM + col) = make_float2(v0, v1);
                }
            }
        }
    }
}

__global__ __launch_bounds__(128, 2)
void qkv_gemm()
{
    extern __shared__ char smc[];
    const int z = blockIdx.z;
    if (z == 0)      gemm_core<0>(g_RQ, g_RW[0], g_Q, 0.125f, smc);
    else if (z == 1) gemm_core<0>(g_RK, g_RW[1], g_K, 1.0f, smc);
    else             gemm_core<0>(g_RV, g_RW[2], g_V, 1.0f, smc);
}

__global__ __launch_bounds__(128, 2)
void out_gemm(float* __restrict__ C)
{
    extern __shared__ char smc[];
    gemm_core<1>(g_Z, g_RW[3], C, 1.0f, smc);
    if (blockIdx.x == 0 && blockIdx.y == 0 && threadIdx.x == 0)
        g_maskflag = 0;   // for the next graph replay
}

// ---------------------------------------------------------------------------
// fp16 mma flash attention. CTA: 128 thr (4 warps), 128 q-rows (32/warp, mt=2),
// 64 iters of 32 keys. K/V double-buffered cp.async; Q/K/P via ldsm,
// V B-frags via ldsm.trans on row-major V tiles.
// ---------------------------------------------------------------------------
#define KSTH 72                       // halves per row (64 + 8)
#define KS_H (32 * KSTH)              // 2304 halves per K (or V) stage
#define PS_H (128 * KSTH)             // 9216 halves
#define ATTN_SMEM ((2*KS_H + 2*KS_H + PS_H) * 2)   // 36864 B

__global__ __launch_bounds__(128, 2)
void attn_mma(const float* __restrict__ mask)
{
    extern __shared__ char smc[];
    __half* Ks = (__half*)smc;
    __half* Vs = Ks + 2 * KS_H;
    __half* Ps = Vs + 2 * KS_H;
    const uint32_t ks_b = smem_u32(Ks);
    const uint32_t vs_b = smem_u32(Vs);
    const uint32_t ps_b = smem_u32(Ps);

    const int tid = threadIdx.x, lane = tid & 31, w = tid >> 5;
    const int r0 = lane >> 2, c0 = lane & 3;
    const int g = lane >> 3, lr = lane & 7;
    const int q0 = blockIdx.x * 128;
    const int bh = blockIdx.y, b = bh >> 4, h = bh & 15;
    const int use_mask = g_maskflag;

    // ldsm offsets (halves)
    const int pAoff = (w * 32 + lr + (g & 1) * 8) * KSTH + (g >> 1) * 8;  // A-style Q/P
    const int kBoff = (lr + (g >> 1) * 8) * KSTH + (g & 1) * 8;           // B-style K
    const int vBoff = (lr + (g & 1) * 8) * KSTH + (g >> 1) * 8;           // trans-B V

    const __half* Kg0 = g_K + (size_t)bh * SS * HD;
    const __half* Vg0 = g_V + (size_t)bh * SS * HD;

    // stage Q tile (128 x 64 halves) into Ps, pull A-frags
    const __half* Qg = g_Q + ((size_t)bh * SS + q0) * HD;
#pragma unroll
    for (int i = 0; i < 8; i++) {
        int c = tid + 128 * i;                   // 0..1023 16B chunks
        int row = c >> 3, c8 = c & 7;
        *(uint4*)(Ps + row * KSTH + c8 * 8) = *(const uint4*)(Qg + (size_t)row * HD + c8 * 8);
    }
    __syncthreads();
    uint32_t qf[2][4][4];                        // [mt][k16 chunk][frag]
#pragma unroll
    for (int mt = 0; mt < 2; mt++)
#pragma unroll
        for (int kc = 0; kc < 4; kc++)
            ldsm_x4(qf[mt][kc], ps_b + (uint32_t)(pAoff + mt * 16 * KSTH + kc * 16) * 2);
    __syncthreads();

    float o[2][8][4];
#pragma unroll
    for (int mt = 0; mt < 2; mt++)
#pragma unroll
        for (int nt = 0; nt < 8; nt++)
#pragma unroll
            for (int j = 0; j < 4; j++) o[mt][nt][j] = 0.f;
    float mrow[2][2], lrow[2][2];
#pragma unroll
    for (int mt = 0; mt < 2; mt++) { mrow[mt][0] = mrow[mt][1] = -INFINITY;
                                     lrow[mt][0] = lrow[mt][1] = 0.f; }

    // K/V tiles: 32 rows x 64 halves = 8 x 16B chunks per row
    auto load_kv = [&](int t, int s) {
#pragma unroll
        for (int i = 0; i < 2; i++) {
            int c = tid + 128 * i;               // 0..255
            int row = c >> 3, c8 = c & 7;
            cp16(ks_b + (uint32_t)(s * KS_H + row * KSTH + c8 * 8) * 2,
                 Kg0 + (size_t)(t * 32 + row) * HD + c8 * 8);
            cp16(vs_b + (uint32_t)(s * KS_H + row * KSTH + c8 * 8) * 2,
                 Vg0 + (size_t)(t * 32 + row) * HD + c8 * 8);
        }
    };

    load_kv(0, 0); CP_COMMIT();

    const int NIT = SS / 32;
    for (int it = 0; it < NIT; it++) {
        if (it + 1 < NIT) load_kv(it + 1, (it + 1) & 1);
        CP_COMMIT();
        asm volatile("cp.async.wait_group 1;" ::: "memory");
        __syncthreads();

        const uint32_t ksb = ks_b + (uint32_t)((it & 1) * KS_H) * 2;
        const uint32_t vsb = vs_b + (uint32_t)((it & 1) * KS_H) * 2;

        // S = Q @ K^T  (per warp: 32 x 32), k-dim = 64 halves = 4 k16 chunks
        float s[2][4][4];
#pragma unroll
        for (int mt = 0; mt < 2; mt++)
#pragma unroll
            for (int nt = 0; nt < 4; nt++)
#pragma unroll
                for (int j = 0; j < 4; j++) s[mt][nt][j] = 0.f;
#pragma unroll
        for (int kc = 0; kc < 4; kc++) {
#pragma unroll
            for (int p = 0; p < 2; p++) {        // key blocks 0-15, 16-31
                uint32_t kp[4];
                ldsm_x4(kp, ksb + (uint32_t)(kBoff + p * 16 * KSTH + kc * 16) * 2);
                const uint32_t f0[2] = { kp[0], kp[1] };
                const uint32_t f1[2] = { kp[2], kp[3] };
                mma_f16(s[0][2 * p],     qf[0][kc], f0);
                mma_f16(s[1][2 * p],     qf[1][kc], f0);
                mma_f16(s[0][2 * p + 1], qf[0][kc], f1);
                mma_f16(s[1][2 * p + 1], qf[1][kc], f1);
            }
        }

        if (use_mask) {
#pragma unroll
            for (int mt = 0; mt < 2; mt++) {
                const float* Mg = mask + ((size_t)b * SS + (q0 + w * 32 + mt * 16 + r0)) * SS
                                       + it * 32;
#pragma unroll
                for (int nt = 0; nt < 4; nt++) {
                    float2 mlo = *(const float2*)(Mg + nt * 8 + 2 * c0);
                    float2 mhi = *(const float2*)(Mg + (size_t)8 * SS + nt * 8 + 2 * c0);
                    s[mt][nt][0] += mlo.x; s[mt][nt][1] += mlo.y;
                    s[mt][nt][2] += mhi.x; s[mt][nt][3] += mhi.y;
                }
            }
        }

        // online softmax + P store (fp16)
#pragma unroll
        for (int mt = 0; mt < 2; mt++) {
            float mx_lo = -INFINITY, mx_hi = -INFINITY;
#pragma unroll
            for (int nt = 0; nt < 4; nt++) {
                mx_lo = fmaxf(mx_lo, fmaxf(s[mt][nt][0], s[mt][nt][1]));
                mx_hi = fmaxf(mx_hi, fmaxf(s[mt][nt][2], s[mt][nt][3]));
            }
            mx_lo = fmaxf(mx_lo, __shfl_xor_sync(0xffffffffu, mx_lo, 1));
            mx_lo = fmaxf(mx_lo, __shfl_xor_sync(0xffffffffu, mx_lo, 2));
            mx_hi = fmaxf(mx_hi, __shfl_xor_sync(0xffffffffu, mx_hi, 1));
            mx_hi = fmaxf(mx_hi, __shfl_xor_sync(0xffffffffu, mx_hi, 2));
            const float nm_lo = fmaxf(mrow[mt][0], mx_lo);
            const float nm_hi = fmaxf(mrow[mt][1], mx_hi);
            const float corr_lo = __expf(mrow[mt][0] - nm_lo);
            const float corr_hi = __expf(mrow[mt][1] - nm_hi);
            mrow[mt][0] = nm_lo; mrow[mt][1] = nm_hi;

            float sum_lo = 0.f, sum_hi = 0.f;
            __half* Pw0 = Ps + (w * 32 + mt * 16 + r0) * KSTH;
            __half* Pw1 = Pw0 + 8 * KSTH;
#pragma unroll
            for (int nt = 0; nt < 4; nt++) {
                float p0 = __expf(s[mt][nt][0] - nm_lo);
                float p1 = __expf(s[mt][nt][1] - nm_lo);
                float p2 = __expf(s[mt][nt][2] - nm_hi);
                float p3 = __expf(s[mt][nt][3] - nm_hi);
                sum_lo += p0 + p1; sum_hi += p2 + p3;
                *(__half2*)(Pw0 + nt * 8 + 2 * c0) = __float22half2_rn(make_float2(p0, p1));
                *(__half2*)(Pw1 + nt * 8 + 2 * c0) = __float22half2_rn(make_float2(p2, p3));
            }
            sum_lo += __shfl_xor_sync(0xffffffffu, sum_lo, 1);
            sum_lo += __shfl_xor_sync(0xffffffffu, sum_lo, 2);
            sum_hi += __shfl_xor_sync(0xffffffffu, sum_hi, 1);
            sum_hi += __shfl_xor_sync(0xffffffffu, sum_hi, 2);
            lrow[mt][0] = lrow[mt][0] * corr_lo + sum_lo;
            lrow[mt][1] = lrow[mt][1] * corr_hi + sum_hi;
#pragma unroll
            for (int nt = 0; nt < 8; nt++) {
                o[mt][nt][0] *= corr_lo; o[mt][nt][1] *= corr_lo;
                o[mt][nt][2] *= corr_hi; o[mt][nt][3] *= corr_hi;
            }
        }
        __syncwarp();

        // O += P @ V  (per warp: 32 x 64, k=32): P A-frags, V trans-B-frags
#pragma unroll
        for (int kc = 0; kc < 2; kc++) {
            uint32_t aa[2][4];
            ldsm_x4(aa[0], ps_b + (uint32_t)(pAoff + kc * 16) * 2);
            ldsm_x4(aa[1], ps_b + (uint32_t)(pAoff + 16 * KSTH + kc * 16) * 2);
#pragma unroll
            for (int dp = 0; dp < 4; dp++) {     // d-pairs: dp covers nt=2dp, 2dp+1
                uint32_t vp[4];
                ldsm_x4_t(vp, vsb + (uint32_t)(vBoff + kc * 16 * KSTH + dp * 16) * 2);
                const uint32_t f0[2] = { vp[0], vp[1] };
                const uint32_t f1[2] = { vp[2], vp[3] };
                mma_f16(o[0][2 * dp],     aa[0], f0);
                mma_f16(o[1][2 * dp],     aa[1], f0);
                mma_f16(o[0][2 * dp + 1], aa[0], f1);
                mma_f16(o[1][2 * dp + 1], aa[1], f1);
            }
        }
        __syncthreads();
    }

    // epilogue: normalize, write fp16 Z[b*SS+q][h*HD+d]
#pragma unroll
    for (int mt = 0; mt < 2; mt++) {
        const float inv_lo = 1.f / lrow[mt][0], inv_hi = 1.f / lrow[mt][1];
        const int qlo = q0 + w * 32 + mt * 16 + r0;
        __half* Zlo = g_Z + ((size_t)b * SS + qlo) * DIM + h * HD;
        __half* Zhi = Zlo + (size_t)8 * DIM;
#pragma unroll
        for (int nt = 0; nt < 8; nt++) {
            const int d = nt * 8 + 2 * c0;
            *(__half2*)(Zlo + d) =
                __float22half2_rn(make_float2(o[mt][nt][0] * inv_lo, o[mt][nt][1] * inv_lo));
            *(__half2*)(Zhi + d) =
                __float22half2_rn(make_float2(o[mt][nt][2] * inv_hi, o[mt][nt][3] * inv_hi));
        }
    }
}

// ---------------------------------------------------------------------------
extern "C" void kernel_launch(void* const* d_in, const int* in_sizes, int n_in,
                              void* d_out, int out_size)
{
    const float* q    = (const float*)d_in[0];
    const float* k    = (const float*)d_in[1];
    const float* v    = (const float*)d_in[2];
    const float* mask = (const float*)d_in[3];
    const float* Wq   = (const float*)d_in[4];
    const float* Wk   = (const float*)d_in[5];
    const float* Wv   = (const float*)d_in[6];
    const float* Wd   = (const float*)d_in[7];

    cudaFuncSetAttribute(qkv_gemm, cudaFuncAttributeMaxDynamicSharedMemorySize, GEMM_SMEM);
    cudaFuncSetAttribute(out_gemm, cudaFuncAttributeMaxDynamicSharedMemorySize, GEMM_SMEM);
    cudaFuncSetAttribute(attn_mma, cudaFuncAttributeMaxDynamicSharedMemorySize, ATTN_SMEM);

    // launch 1: f32->fp16 convert everything + mask scan
    round_all<<<dim3(2048, 1, 8), 256>>>(q, k, v, Wq, Wk, Wv, Wd, mask);

    // launch 2: q/k/v projections (fp16 mma, fp16 outputs)
    qkv_gemm<<<dim3(MROWS/128, DIM/128, 3), 128, GEMM_SMEM>>>();

    // launch 3: flash attention (fp16 mma)
    attn_mma<<<dim3(SS/128, BB*NH), 128, ATTN_SMEM>>>(mask);

    // launch 4: output projection, f32 out (+ maskflag reset)
    out_gemm<<<dim3(MROWS/128, DIM/128), 128, GEMM_SMEM>>>((float*)d_out);
}

// round 10
// speedup vs baseline: 1.9924x; 1.0613x over previous
#include <cuda_runtime.h>
#include <cuda_fp16.h>
#include <math.h>
#include <stdint.h>

#define DIM 1024
#define BB 4
#define SS 2048
#define NH 16
#define HD 64
#define MROWS (BB*SS)   // 8192
#define LOG2E 1.44269504088896340736f

// ---------------------------------------------------------------------------
// Scratch (device globals; no allocation allowed) — fp16 operands everywhere
// ---------------------------------------------------------------------------
__device__ __half g_Q[BB*NH*SS*HD];   // [b,h,s,d] projected Q (x 0.125*log2e)
__device__ __half g_K[BB*NH*SS*HD];
__device__ __half g_V[BB*NH*SS*HD];
__device__ __half g_Z[MROWS*DIM];     // attention out
__device__ __half g_RQ[MROWS*DIM];    // fp16 inputs
__device__ __half g_RK[MROWS*DIM];
__device__ __half g_RV[MROWS*DIM];
__device__ __half g_RW[4][DIM*DIM];   // fp16 weights
__device__ int    g_maskflag;         // zero-init; reset by out_gemm each run

// ---------------------------------------------------------------------------
// Helpers (compute_103-legal, sm_80-era PTX)
// ---------------------------------------------------------------------------
__device__ __forceinline__ uint32_t smem_u32(const void* p) {
    uint32_t a;
    asm("{ .reg .u64 t; cvta.to.shared.u64 t, %1; cvt.u32.u64 %0, t; }" : "=r"(a) : "l"(p));
    return a;
}
__device__ __forceinline__ void cp16(uint32_t dst, const void* src) {
    asm volatile("cp.async.cg.shared.global [%0], [%1], 16;" :: "r"(dst), "l"(src));
}
#define CP_COMMIT() asm volatile("cp.async.commit_group;" ::: "memory")

__device__ __forceinline__ void mma_f16(float d[4], const uint32_t a[4], const uint32_t b[2]) {
    asm volatile(
        "mma.sync.aligned.m16n8k16.row.col.f32.f16.f16.f32 "
        "{%0,%1,%2,%3}, {%4,%5,%6,%7}, {%8,%9}, {%0,%1,%2,%3};"
        : "+f"(d[0]), "+f"(d[1]), "+f"(d[2]), "+f"(d[3])
        : "r"(a[0]), "r"(a[1]), "r"(a[2]), "r"(a[3]), "r"(b[0]), "r"(b[1]));
}
__device__ __forceinline__ void ldsm_x4(uint32_t r[4], uint32_t addr) {
    asm volatile("ldmatrix.sync.aligned.m8n8.x4.shared.b16 {%0,%1,%2,%3}, [%4];"
                 : "=r"(r[0]), "=r"(r[1]), "=r"(r[2]), "=r"(r[3]) : "r"(addr));
}
__device__ __forceinline__ void ldsm_x4_t(uint32_t r[4], uint32_t addr) {
    asm volatile("ldmatrix.sync.aligned.m8n8.x4.trans.shared.b16 {%0,%1,%2,%3}, [%4];"
                 : "=r"(r[0]), "=r"(r[1]), "=r"(r[2]), "=r"(r[3]) : "r"(addr));
}

// ---------------------------------------------------------------------------
// Merged f32->fp16 convert (q,k,v,W*) + mask scan. grid (2048,1,8), 256 thr.
// ---------------------------------------------------------------------------
__global__ __launch_bounds__(256)
void round_all(const float* __restrict__ q, const float* __restrict__ k,
               const float* __restrict__ v, const float* __restrict__ Wq,
               const float* __restrict__ Wk, const float* __restrict__ Wv,
               const float* __restrict__ Wd, const float* __restrict__ mask)
{
    const int z = blockIdx.z;
    const int tid = threadIdx.x;
    if (z == 7) {   // mask scan
        const float4* m4 = (const float4*)mask;
        const size_t base = (size_t)blockIdx.x * 2048 + tid;
        bool nz = false;
#pragma unroll
        for (int i = 0; i < 8; i++) {
            float4 vv = m4[base + (size_t)i * 256];
            nz |= (vv.x != 0.f) | (vv.y != 0.f) | (vv.z != 0.f) | (vv.w != 0.f);
        }
        if (__syncthreads_or(nz) && tid == 0) atomicExch(&g_maskflag, 1);
        return;
    }
    const float* src; __half* dst; int nblk;
    switch (z) {
        case 0: src = q;  dst = g_RQ;    nblk = 2048; break;
        case 1: src = k;  dst = g_RK;    nblk = 2048; break;
        case 2: src = v;  dst = g_RV;    nblk = 2048; break;
        case 3: src = Wq; dst = g_RW[0]; nblk = 256;  break;
        case 4: src = Wk; dst = g_RW[1]; nblk = 256;  break;
        case 5: src = Wv; dst = g_RW[2]; nblk = 256;  break;
        default: src = Wd; dst = g_RW[3]; nblk = 256; break;
    }
    if (blockIdx.x >= (unsigned)nblk) return;
    const float4* s4 = (const float4*)src;
    __half2* d2 = (__half2*)dst;
    const size_t base = (size_t)blockIdx.x * 1024 + tid;
#pragma unroll
    for (int i = 0; i < 4; i++) {
        const size_t f = base + (size_t)i * 256;
        float4 vv = s4[f];
        d2[2 * f]     = __float22half2_rn(make_float2(vv.x, vv.y));
        d2[2 * f + 1] = __float22half2_rn(make_float2(vv.z, vv.w));
    }
}

// ---------------------------------------------------------------------------
// fp16 GEMM core: C = scale * (A[M,K] @ W[N,K]^T), K=1024.
// BM=BN=128, BK=32 halves, 128 thr (2x2 warps, warp tile 64x64), 4-stage pipe.
// All 16 ldsm of a k-tile hoisted before the 64-mma burst.
// ---------------------------------------------------------------------------
#define PSTH 40                       // smem row stride in halves (32 + 8)
#define STG_H (2 * 128 * PSTH)        // A+B halves per stage = 10240
#define STG_B (STG_H * 2)             // 20480 bytes
#define GEMM_SMEM (4 * STG_B)         // 81920 bytes

template<int LAYOUT>
__device__ __forceinline__
void gemm_core(const __half* __restrict__ A, const __half* __restrict__ W,
               void* __restrict__ Cv, float scale, char* smc)
{
    const int tid = threadIdx.x;
    const int lane = tid & 31, wid = tid >> 5;
    const int wr = wid >> 1, wc = wid & 1;
    const int r0 = lane >> 2, c0 = lane & 3;
    const int g = lane >> 3, lr = lane & 7;
    const int row0 = blockIdx.x * 128, col0 = blockIdx.y * 128;
    const uint32_t smb = smem_u32(smc);

    const int aoff = (wr * 64 + lr + (g & 1) * 8) * PSTH + (g >> 1) * 8;   // A-style
    const int boff = (wc * 64 + lr + (g >> 1) * 8) * PSTH + (g & 1) * 8;   // B-style

    float acc[4][8][4];
#pragma unroll
    for (int mt = 0; mt < 4; mt++)
#pragma unroll
        for (int nt = 0; nt < 8; nt++)
#pragma unroll
            for (int j = 0; j < 4; j++) acc[mt][nt][j] = 0.f;

    auto load_stage = [&](int kt, int s) {
        uint32_t a_s = smb + s * STG_B;
        uint32_t b_s = a_s + 128 * PSTH * 2;
#pragma unroll
        for (int i = 0; i < 4; i++) {
            int c = tid + 128 * i;
            int row = c >> 2, c4 = c & 3;
            uint32_t so = (uint32_t)(row * PSTH + c4 * 8) * 2;
            cp16(a_s + so, A + (size_t)(row0 + row) * DIM + kt * 32 + c4 * 8);
            cp16(b_s + so, W + (size_t)(col0 + row) * DIM + kt * 32 + c4 * 8);
        }
    };

    load_stage(0, 0); CP_COMMIT();
    load_stage(1, 1); CP_COMMIT();
    load_stage(2, 2); CP_COMMIT();

    const int NT = DIM / 32;                     // 32
    for (int kt = 0; kt < NT; kt++) {
        asm volatile("cp.async.wait_group 2;" ::: "memory");
        __syncthreads();
        if (kt + 3 < NT) load_stage(kt + 3, (kt + 3) & 3);
        CP_COMMIT();

        const uint32_t a_s = smb + (kt & 3) * STG_B;
        const uint32_t b_s = a_s + 128 * PSTH * 2;

        // prefetch ALL fragments for this k-tile (both k16 chunks)
        uint32_t a[2][4][4], bp[2][4][4];
#pragma unroll
        for (int ks = 0; ks < 2; ks++) {
            const int kb = ks * 16;
#pragma unroll
            for (int mt = 0; mt < 4; mt++)
                ldsm_x4(a[ks][mt], a_s + (uint32_t)(aoff + mt * 16 * PSTH + kb) * 2);
#pragma unroll
            for (int p = 0; p < 4; p++)
                ldsm_x4(bp[ks][p], b_s + (uint32_t)(boff + p * 16 * PSTH + kb) * 2);
        }
        // 128 mma burst, no smem dependence
#pragma unroll
        for (int ks = 0; ks < 2; ks++)
#pragma unroll
            for (int nt = 0; nt < 8; nt++) {
                const uint32_t bfr[2] = { bp[ks][nt >> 1][(nt & 1) * 2],
                                          bp[ks][nt >> 1][(nt & 1) * 2 + 1] };
#pragma unroll
                for (int mt = 0; mt < 4; mt++)
                    mma_f16(acc[mt][nt], a[ks][mt], bfr);
            }
    }

#pragma unroll
    for (int mt = 0; mt < 4; mt++) {
        const int rA = row0 + wr * 64 + mt * 16 + r0;
#pragma unroll
        for (int rr = 0; rr < 2; rr++) {
            const int r = rA + rr * 8;
#pragma unroll
            for (int nt = 0; nt < 8; nt++) {
                const int col = col0 + wc * 64 + nt * 8 + 2 * c0;
                float v0 = acc[mt][nt][rr * 2 + 0] * scale;
                float v1 = acc[mt][nt][rr * 2 + 1] * scale;
                if (LAYOUT == 0) {
                    const int b = r >> 11, s = r & (SS - 1);
                    const int h = col >> 6, d = col & 63;
                    __half* C = (__half*)Cv;
                    *(__half2*)(C + ((size_t)((b * NH + h) * SS) + s) * HD + d) =
                        __float22half2_rn(make_float2(v0, v1));
                } else {
                    float* C = (float*)Cv;
                    *(float2*)(C + (size_t)r * DIM + col) = make_float2(v0, v1);
                }
            }
        }
    }
}

__global__ __launch_bounds__(128, 2)
void qkv_gemm()
{
    extern __shared__ char smc[];
    const int z = blockIdx.z;
    if (z == 0)      gemm_core<0>(g_RQ, g_RW[0], g_Q, 0.125f * LOG2E, smc);  // fold log2e
    else if (z == 1) gemm_core<0>(g_RK, g_RW[1], g_K, 1.0f, smc);
    else             gemm_core<0>(g_RV, g_RW[2], g_V, 1.0f, smc);
}

__global__ __launch_bounds__(128, 2)
void out_gemm(float* __restrict__ C)
{
    extern __shared__ char smc[];
    gemm_core<1>(g_Z, g_RW[3], C, 1.0f, smc);
    if (blockIdx.x == 0 && blockIdx.y == 0 && threadIdx.x == 0)
        g_maskflag = 0;   // for the next graph replay
}

// ---------------------------------------------------------------------------
// fp16 mma flash attention, 64-key tiles, base-2 softmax.
// CTA: 128 thr (4 warps), 128 q-rows (32/warp, mt=2), 32 iters of 64 keys.
// Q/K/P via ldsm, V B-frags via ldsm.trans. Scores are pre-scaled by log2e.
// ---------------------------------------------------------------------------
#define KSTH 72                       // halves per row (64 + 8)
#define KS_H (64 * KSTH)              // 4608 halves per K (or V) stage
#define PS_H (128 * KSTH)             // 9216 halves
#define ATTN_SMEM ((2*KS_H + 2*KS_H + PS_H) * 2)   // 55296 B

__global__ __launch_bounds__(128, 2)
void attn_mma(const float* __restrict__ mask)
{
    extern __shared__ char smc[];
    __half* Ks = (__half*)smc;
    __half* Vs = Ks + 2 * KS_H;
    __half* Ps = Vs + 2 * KS_H;
    const uint32_t ks_b = smem_u32(Ks);
    const uint32_t vs_b = smem_u32(Vs);
    const uint32_t ps_b = smem_u32(Ps);

    const int tid = threadIdx.x, lane = tid & 31, w = tid >> 5;
    const int r0 = lane >> 2, c0 = lane & 3;
    const int g = lane >> 3, lr = lane & 7;
    const int q0 = blockIdx.x * 128;
    const int bh = blockIdx.y, b = bh >> 4, h = bh & 15;
    const int use_mask = g_maskflag;

    const int pAoff = (w * 32 + lr + (g & 1) * 8) * KSTH + (g >> 1) * 8;  // A-style Q/P
    const int kBoff = (lr + (g >> 1) * 8) * KSTH + (g & 1) * 8;           // B-style K
    const int vBoff = (lr + (g & 1) * 8) * KSTH + (g >> 1) * 8;           // trans-B V

    const __half* Kg0 = g_K + (size_t)bh * SS * HD;
    const __half* Vg0 = g_V + (size_t)bh * SS * HD;

    // stage Q tile into Ps, pull A-frags
    const __half* Qg = g_Q + ((size_t)bh * SS + q0) * HD;
#pragma unroll
    for (int i = 0; i < 8; i++) {
        int c = tid + 128 * i;
        int row = c >> 3, c8 = c & 7;
        *(uint4*)(Ps + row * KSTH + c8 * 8) = *(const uint4*)(Qg + (size_t)row * HD + c8 * 8);
    }
    __syncthreads();
    uint32_t qf[2][4][4];
#pragma unroll
    for (int mt = 0; mt < 2; mt++)
#pragma unroll
        for (int kc = 0; kc < 4; kc++)
            ldsm_x4(qf[mt][kc], ps_b + (uint32_t)(pAoff + mt * 16 * KSTH + kc * 16) * 2);
    __syncthreads();

    float o[2][8][4];
#pragma unroll
    for (int mt = 0; mt < 2; mt++)
#pragma unroll
        for (int nt = 0; nt < 8; nt++)
#pragma unroll
            for (int j = 0; j < 4; j++) o[mt][nt][j] = 0.f;
    float mrow[2][2], lrow[2][2];
#pragma unroll
    for (int mt = 0; mt < 2; mt++) { mrow[mt][0] = mrow[mt][1] = -INFINITY;
                                     lrow[mt][0] = lrow[mt][1] = 0.f; }

    // K/V tiles: 64 rows x 64 halves = 8 x 16B chunks per row
    auto load_kv = [&](int t, int s) {
#pragma unroll
        for (int i = 0; i < 4; i++) {
            int c = tid + 128 * i;               // 0..511
            int row = c >> 3, c8 = c & 7;
            cp16(ks_b + (uint32_t)(s * KS_H + row * KSTH + c8 * 8) * 2,
                 Kg0 + (size_t)(t * 64 + row) * HD + c8 * 8);
            cp16(vs_b + (uint32_t)(s * KS_H + row * KSTH + c8 * 8) * 2,
                 Vg0 + (size_t)(t * 64 + row) * HD + c8 * 8);
        }
    };

    load_kv(0, 0); CP_COMMIT();

    const int NIT = SS / 64;                     // 32
    for (int it = 0; it < NIT; it++) {
        if (it + 1 < NIT) load_kv(it + 1, (it + 1) & 1);
        CP_COMMIT();
        asm volatile("cp.async.wait_group 1;" ::: "memory");
        __syncthreads();

        const uint32_t ksb = ks_b + (uint32_t)((it & 1) * KS_H) * 2;
        const uint32_t vsb = vs_b + (uint32_t)((it & 1) * KS_H) * 2;

        // S = Q @ K^T  (per warp: 32 x 64); scores already in log2 units
        float s[2][8][4];
#pragma unroll
        for (int mt = 0; mt < 2; mt++)
#pragma unroll
            for (int nt = 0; nt < 8; nt++)
#pragma unroll
                for (int j = 0; j < 4; j++) s[mt][nt][j] = 0.f;
#pragma unroll
        for (int kc = 0; kc < 4; kc++) {
#pragma unroll
            for (int p = 0; p < 4; p++) {        // key blocks of 16
                uint32_t kp[4];
                ldsm_x4(kp, ksb + (uint32_t)(kBoff + p * 16 * KSTH + kc * 16) * 2);
                const uint32_t f0[2] = { kp[0], kp[1] };
                const uint32_t f1[2] = { kp[2], kp[3] };
                mma_f16(s[0][2 * p],     qf[0][kc], f0);
                mma_f16(s[1][2 * p],     qf[1][kc], f0);
                mma_f16(s[0][2 * p + 1], qf[0][kc], f1);
                mma_f16(s[1][2 * p + 1], qf[1][kc], f1);
            }
        }

        if (use_mask) {
#pragma unroll
            for (int mt = 0; mt < 2; mt++) {
                const float* Mg = mask + ((size_t)b * SS + (q0 + w * 32 + mt * 16 + r0)) * SS
                                       + it * 64;
#pragma unroll
                for (int nt = 0; nt < 8; nt++) {
                    float2 mlo = *(const float2*)(Mg + nt * 8 + 2 * c0);
                    float2 mhi = *(const float2*)(Mg + (size_t)8 * SS + nt * 8 + 2 * c0);
                    s[mt][nt][0] = fmaf(mlo.x, LOG2E, s[mt][nt][0]);
                    s[mt][nt][1] = fmaf(mlo.y, LOG2E, s[mt][nt][1]);
                    s[mt][nt][2] = fmaf(mhi.x, LOG2E, s[mt][nt][2]);
                    s[mt][nt][3] = fmaf(mhi.y, LOG2E, s[mt][nt][3]);
                }
            }
        }

        // online softmax (base-2) + P store (fp16)
#pragma unroll
        for (int mt = 0; mt < 2; mt++) {
            float mx_lo = -INFINITY, mx_hi = -INFINITY;
#pragma unroll
            for (int nt = 0; nt < 8; nt++) {
                mx_lo = fmaxf(mx_lo, fmaxf(s[mt][nt][0], s[mt][nt][1]));
                mx_hi = fmaxf(mx_hi, fmaxf(s[mt][nt][2], s[mt][nt][3]));
            }
            mx_lo = fmaxf(mx_lo, __shfl_xor_sync(0xffffffffu, mx_lo, 1));
            mx_lo = fmaxf(mx_lo, __shfl_xor_sync(0xffffffffu, mx_lo, 2));
            mx_hi = fmaxf(mx_hi, __shfl_xor_sync(0xffffffffu, mx_hi, 1));
            mx_hi = fmaxf(mx_hi, __shfl_xor_sync(0xffffffffu, mx_hi, 2));
            const float nm_lo = fmaxf(mrow[mt][0], mx_lo);
            const float nm_hi = fmaxf(mrow[mt][1], mx_hi);
            const float corr_lo = exp2f(mrow[mt][0] - nm_lo);
            const float corr_hi = exp2f(mrow[mt][1] - nm_hi);
            mrow[mt][0] = nm_lo; mrow[mt][1] = nm_hi;

            float sum_lo = 0.f, sum_hi = 0.f;
            __half* Pw0 = Ps + (w * 32 + mt * 16 + r0) * KSTH;
            __half* Pw1 = Pw0 + 8 * KSTH;
#pragma unroll
            for (int nt = 0; nt < 8; nt++) {
                float p0 = exp2f(s[mt][nt][0] - nm_lo);
                float p1 = exp2f(s[mt][nt][1] - nm_lo);
                float p2 = exp2f(s[mt][nt][2] - nm_hi);
                float p3 = exp2f(s[mt][nt][3] - nm_hi);
                sum_lo += p0 + p1; sum_hi += p2 + p3;
                *(__half2*)(Pw0 + nt * 8 + 2 * c0) = __float22half2_rn(make_float2(p0, p1));
                *(__half2*)(Pw1 + nt * 8 + 2 * c0) = __float22half2_rn(make_float2(p2, p3));
            }
            sum_lo += __shfl_xor_sync(0xffffffffu, sum_lo, 1);
            sum_lo += __shfl_xor_sync(0xffffffffu, sum_lo, 2);
            sum_hi += __shfl_xor_sync(0xffffffffu, sum_hi, 1);
            sum_hi += __shfl_xor_sync(0xffffffffu, sum_hi, 2);
            lrow[mt][0] = lrow[mt][0] * corr_lo + sum_lo;
            lrow[mt][1] = lrow[mt][1] * corr_hi + sum_hi;
#pragma unroll
            for (int nt = 0; nt < 8; nt++) {
                o[mt][nt][0] *= corr_lo; o[mt][nt][1] *= corr_lo;
                o[mt][nt][2] *= corr_hi; o[mt][nt][3] *= corr_hi;
            }
        }
        __syncwarp();

        // O += P @ V  (per warp: 32 x 64, k=64): P A-frags, V trans-B-frags
#pragma unroll
        for (int kc = 0; kc < 4; kc++) {
            uint32_t aa[2][4];
            ldsm_x4(aa[0], ps_b + (uint32_t)(pAoff + kc * 16) * 2);
            ldsm_x4(aa[1], ps_b + (uint32_t)(pAoff + 16 * KSTH + kc * 16) * 2);
#pragma unroll
            for (int dp = 0; dp < 4; dp++) {
                uint32_t vp[4];
                ldsm_x4_t(vp, vsb + (uint32_t)(vBoff + kc * 16 * KSTH + dp * 16) * 2);
                const uint32_t f0[2] = { vp[0], vp[1] };
                const uint32_t f1[2] = { vp[2], vp[3] };
                mma_f16(o[0][2 * dp],     aa[0], f0);
                mma_f16(o[1][2 * dp],     aa[1], f0);
                mma_f16(o[0][2 * dp + 1], aa[0], f1);
                mma_f16(o[1][2 * dp + 1], aa[1], f1);
            }
        }
        __syncthreads();
    }

    // epilogue: normalize, write fp16 Z[b*SS+q][h*HD+d]
#pragma unroll
    for (int mt = 0; mt < 2; mt++) {
        const float inv_lo = 1.f / lrow[mt][0], inv_hi = 1.f / lrow[mt][1];
        const int qlo = q0 + w * 32 + mt * 16 + r0;
        __half* Zlo = g_Z + ((size_t)b * SS + qlo) * DIM + h * HD;
        __half* Zhi = Zlo + (size_t)8 * DIM;
#pragma unroll
        for (int nt = 0; nt < 8; nt++) {
            const int d = nt * 8 + 2 * c0;
            *(__half2*)(Zlo + d) =
                __float22half2_rn(make_float2(o[mt][nt][0] * inv_lo, o[mt][nt][1] * inv_lo));
            *(__half2*)(Zhi + d) =
                __float22half2_rn(make_float2(o[mt][nt][2] * inv_hi, o[mt][nt][3] * inv_hi));
        }
    }
}

// ---------------------------------------------------------------------------
extern "C" void kernel_launch(void* const* d_in, const int* in_sizes, int n_in,
                              void* d_out, int out_size)
{
    const float* q    = (const float*)d_in[0];
    const float* k    = (const float*)d_in[1];
    const float* v    = (const float*)d_in[2];
    const float* mask = (const float*)d_in[3];
    const float* Wq   = (const float*)d_in[4];
    const float* Wk   = (const float*)d_in[5];
    const float* Wv   = (const float*)d_in[6];
    const float* Wd   = (const float*)d_in[7];

    cudaFuncSetAttribute(qkv_gemm, cudaFuncAttributeMaxDynamicSharedMemorySize, GEMM_SMEM);
    cudaFuncSetAttribute(out_gemm, cudaFuncAttributeMaxDynamicSharedMemorySize, GEMM_SMEM);
    cudaFuncSetAttribute(attn_mma, cudaFuncAttributeMaxDynamicSharedMemorySize, ATTN_SMEM);

    // launch 1: f32->fp16 convert everything + mask scan
    round_all<<<dim3(2048, 1, 8), 256>>>(q, k, v, Wq, Wk, Wv, Wd, mask);

    // launch 2: q/k/v projections (fp16 mma; Q pre-scaled by 0.125*log2e)
    qkv_gemm<<<dim3(MROWS/128, DIM/128, 3), 128, GEMM_SMEM>>>();

    // launch 3: flash attention (fp16 mma, base-2 softmax)
    attn_mma<<<dim3(SS/128, BB*NH), 128, ATTN_SMEM>>>(mask);

    // launch 4: output projection, f32 out (+ maskflag reset)
    out_gemm<<<dim3(MROWS/128, DIM/128), 128, GEMM_SMEM>>>((float*)d_out);
}

// round 11
// speedup vs baseline: 2.0894x; 1.0487x over previous
#include <cuda_runtime.h>
#include <cuda_fp16.h>
#include <math.h>
#include <stdint.h>

#define DIM 1024
#define BB 4
#define SS 2048
#define NH 16
#define HD 64
#define MROWS (BB*SS)   // 8192
#define LOG2E 1.44269504088896340736f

// ---------------------------------------------------------------------------
// Scratch (device globals; no allocation allowed) — fp16 operands everywhere
// ---------------------------------------------------------------------------
__device__ __half g_Q[BB*NH*SS*HD];   // [b,h,s,d] projected Q (x 0.125*log2e)
__device__ __half g_K[BB*NH*SS*HD];
__device__ __half g_V[BB*NH*SS*HD];
__device__ __half g_Z[MROWS*DIM];     // attention out
__device__ __half g_RQ[MROWS*DIM];    // fp16 inputs
__device__ __half g_RK[MROWS*DIM];
__device__ __half g_RV[MROWS*DIM];
__device__ __half g_RW[4][DIM*DIM];   // fp16 weights
__device__ int    g_maskflag;         // zero-init; reset by out_gemm each run

// ---------------------------------------------------------------------------
// Helpers (compute_103-legal, sm_80-era PTX)
// ---------------------------------------------------------------------------
__device__ __forceinline__ uint32_t smem_u32(const void* p) {
    uint32_t a;
    asm("{ .reg .u64 t; cvta.to.shared.u64 t, %1; cvt.u32.u64 %0, t; }" : "=r"(a) : "l"(p));
    return a;
}
__device__ __forceinline__ void cp16(uint32_t dst, const void* src) {
    asm volatile("cp.async.cg.shared.global [%0], [%1], 16;" :: "r"(dst), "l"(src));
}
#define CP_COMMIT() asm volatile("cp.async.commit_group;" ::: "memory")

__device__ __forceinline__ void mma_f16(float d[4], const uint32_t a[4], const uint32_t b[2]) {
    asm volatile(
        "mma.sync.aligned.m16n8k16.row.col.f32.f16.f16.f32 "
        "{%0,%1,%2,%3}, {%4,%5,%6,%7}, {%8,%9}, {%0,%1,%2,%3};"
        : "+f"(d[0]), "+f"(d[1]), "+f"(d[2]), "+f"(d[3])
        : "r"(a[0]), "r"(a[1]), "r"(a[2]), "r"(a[3]), "r"(b[0]), "r"(b[1]));
}
__device__ __forceinline__ void ldsm_x4(uint32_t r[4], uint32_t addr) {
    asm volatile("ldmatrix.sync.aligned.m8n8.x4.shared.b16 {%0,%1,%2,%3}, [%4];"
                 : "=r"(r[0]), "=r"(r[1]), "=r"(r[2]), "=r"(r[3]) : "r"(addr));
}
__device__ __forceinline__ void ldsm_x4_t(uint32_t r[4], uint32_t addr) {
    asm volatile("ldmatrix.sync.aligned.m8n8.x4.trans.shared.b16 {%0,%1,%2,%3}, [%4];"
                 : "=r"(r[0]), "=r"(r[1]), "=r"(r[2]), "=r"(r[3]) : "r"(addr));
}
__device__ __forceinline__ uint32_t pack_h2(float x, float y) {
    __half2 h = __float22half2_rn(make_float2(x, y));
    return *(uint32_t*)&h;
}

// ---------------------------------------------------------------------------
// Merged f32->fp16 convert (q,k,v,W*) + mask scan. grid (2048,1,8), 256 thr.
// ---------------------------------------------------------------------------
__global__ __launch_bounds__(256)
void round_all(const float* __restrict__ q, const float* __restrict__ k,
               const float* __restrict__ v, const float* __restrict__ Wq,
               const float* __restrict__ Wk, const float* __restrict__ Wv,
               const float* __restrict__ Wd, const float* __restrict__ mask)
{
    const int z = blockIdx.z;
    const int tid = threadIdx.x;
    if (z == 7) {   // mask scan
        const float4* m4 = (const float4*)mask;
        const size_t base = (size_t)blockIdx.x * 2048 + tid;
        bool nz = false;
#pragma unroll
        for (int i = 0; i < 8; i++) {
            float4 vv = m4[base + (size_t)i * 256];
            nz |= (vv.x != 0.f) | (vv.y != 0.f) | (vv.z != 0.f) | (vv.w != 0.f);
        }
        if (__syncthreads_or(nz) && tid == 0) atomicExch(&g_maskflag, 1);
        return;
    }
    const float* src; __half* dst; int nblk;
    switch (z) {
        case 0: src = q;  dst = g_RQ;    nblk = 2048; break;
        case 1: src = k;  dst = g_RK;    nblk = 2048; break;
        case 2: src = v;  dst = g_RV;    nblk = 2048; break;
        case 3: src = Wq; dst = g_RW[0]; nblk = 256;  break;
        case 4: src = Wk; dst = g_RW[1]; nblk = 256;  break;
        case 5: src = Wv; dst = g_RW[2]; nblk = 256;  break;
        default: src = Wd; dst = g_RW[3]; nblk = 256; break;
    }
    if (blockIdx.x >= (unsigned)nblk) return;
    const float4* s4 = (const float4*)src;
    __half2* d2 = (__half2*)dst;
    const size_t base = (size_t)blockIdx.x * 1024 + tid;
#pragma unroll
    for (int i = 0; i < 4; i++) {
        const size_t f = base + (size_t)i * 256;
        float4 vv = s4[f];
        d2[2 * f]     = __float22half2_rn(make_float2(vv.x, vv.y));
        d2[2 * f + 1] = __float22half2_rn(make_float2(vv.z, vv.w));
    }
}

// ---------------------------------------------------------------------------
// fp16 GEMM core (round-10 config, unchanged): BM=BN=128, BK=32 halves,
// 128 thr (2x2 warps, warp tile 64x64), 4-stage pipe, frag hoist.
// ---------------------------------------------------------------------------
#define PSTH 40
#define STG_H (2 * 128 * PSTH)
#define STG_B (STG_H * 2)
#define GEMM_SMEM (4 * STG_B)         // 81920 bytes

template<int LAYOUT>
__device__ __forceinline__
void gemm_core(const __half* __restrict__ A, const __half* __restrict__ W,
               void* __restrict__ Cv, float scale, char* smc)
{
    const int tid = threadIdx.x;
    const int lane = tid & 31, wid = tid >> 5;
    const int wr = wid >> 1, wc = wid & 1;
    const int r0 = lane >> 2, c0 = lane & 3;
    const int g = lane >> 3, lr = lane & 7;
    const int row0 = blockIdx.x * 128, col0 = blockIdx.y * 128;
    const uint32_t smb = smem_u32(smc);

    const int aoff = (wr * 64 + lr + (g & 1) * 8) * PSTH + (g >> 1) * 8;
    const int boff = (wc * 64 + lr + (g >> 1) * 8) * PSTH + (g & 1) * 8;

    float acc[4][8][4];
#pragma unroll
    for (int mt = 0; mt < 4; mt++)
#pragma unroll
        for (int nt = 0; nt < 8; nt++)
#pragma unroll
            for (int j = 0; j < 4; j++) acc[mt][nt][j] = 0.f;

    auto load_stage = [&](int kt, int s) {
        uint32_t a_s = smb + s * STG_B;
        uint32_t b_s = a_s + 128 * PSTH * 2;
#pragma unroll
        for (int i = 0; i < 4; i++) {
            int c = tid + 128 * i;
            int row = c >> 2, c4 = c & 3;
            uint32_t so = (uint32_t)(row * PSTH + c4 * 8) * 2;
            cp16(a_s + so, A + (size_t)(row0 + row) * DIM + kt * 32 + c4 * 8);
            cp16(b_s + so, W + (size_t)(col0 + row) * DIM + kt * 32 + c4 * 8);
        }
    };

    load_stage(0, 0); CP_COMMIT();
    load_stage(1, 1); CP_COMMIT();
    load_stage(2, 2); CP_COMMIT();

    const int NT = DIM / 32;
    for (int kt = 0; kt < NT; kt++) {
        asm volatile("cp.async.wait_group 2;" ::: "memory");
        __syncthreads();
        if (kt + 3 < NT) load_stage(kt + 3, (kt + 3) & 3);
        CP_COMMIT();

        const uint32_t a_s = smb + (kt & 3) * STG_B;
        const uint32_t b_s = a_s + 128 * PSTH * 2;

        uint32_t a[2][4][4], bp[2][4][4];
#pragma unroll
        for (int ks = 0; ks < 2; ks++) {
            const int kb = ks * 16;
#pragma unroll
            for (int mt = 0; mt < 4; mt++)
                ldsm_x4(a[ks][mt], a_s + (uint32_t)(aoff + mt * 16 * PSTH + kb) * 2);
#pragma unroll
            for (int p = 0; p < 4; p++)
                ldsm_x4(bp[ks][p], b_s + (uint32_t)(boff + p * 16 * PSTH + kb) * 2);
        }
#pragma unroll
        for (int ks = 0; ks < 2; ks++)
#pragma unroll
            for (int nt = 0; nt < 8; nt++) {
                const uint32_t bfr[2] = { bp[ks][nt >> 1][(nt & 1) * 2],
                                          bp[ks][nt >> 1][(nt & 1) * 2 + 1] };
#pragma unroll
                for (int mt = 0; mt < 4; mt++)
                    mma_f16(acc[mt][nt], a[ks][mt], bfr);
            }
    }

#pragma unroll
    for (int mt = 0; mt < 4; mt++) {
        const int rA = row0 + wr * 64 + mt * 16 + r0;
#pragma unroll
        for (int rr = 0; rr < 2; rr++) {
            const int r = rA + rr * 8;
#pragma unroll
            for (int nt = 0; nt < 8; nt++) {
                const int col = col0 + wc * 64 + nt * 8 + 2 * c0;
                float v0 = acc[mt][nt][rr * 2 + 0] * scale;
                float v1 = acc[mt][nt][rr * 2 + 1] * scale;
                if (LAYOUT == 0) {
                    const int b = r >> 11, s = r & (SS - 1);
                    const int h = col >> 6, d = col & 63;
                    __half* C = (__half*)Cv;
                    *(__half2*)(C + ((size_t)((b * NH + h) * SS) + s) * HD + d) =
                        __float22half2_rn(make_float2(v0, v1));
                } else {
                    float* C = (float*)Cv;
                    *(float2*)(C + (size_t)r * DIM + col) = make_float2(v0, v1);
                }
            }
        }
    }
}

__global__ __launch_bounds__(128, 2)
void qkv_gemm()
{
    extern __shared__ char smc[];
    const int z = blockIdx.z;
    if (z == 0)      gemm_core<0>(g_RQ, g_RW[0], g_Q, 0.125f * LOG2E, smc);
    else if (z == 1) gemm_core<0>(g_RK, g_RW[1], g_K, 1.0f, smc);
    else             gemm_core<0>(g_RV, g_RW[2], g_V, 1.0f, smc);
}

__global__ __launch_bounds__(128, 2)
void out_gemm(float* __restrict__ C)
{
    extern __shared__ char smc[];
    gemm_core<1>(g_Z, g_RW[3], C, 1.0f, smc);
    if (blockIdx.x == 0 && blockIdx.y == 0 && threadIdx.x == 0)
        g_maskflag = 0;
}

// ---------------------------------------------------------------------------
// fp16 mma flash attention, 64-key tiles, base-2 softmax, P IN REGISTERS
// (C-frag of QK == A-frag of PV after half2 packing), pipelined K/V ldsm.
// CTA: 128 thr (4 warps), 128 q-rows (32/warp, mt=2), 32 iters of 64 keys.
// ---------------------------------------------------------------------------
#define KSTH 72                       // halves per row (64 + 8)
#define KS_H (64 * KSTH)              // 4608 halves per K (or V) stage
#define ATTN_SMEM ((2*KS_H + 2*KS_H) * 2)   // 36864 B (Q staged in Ks area)

__global__ __launch_bounds__(128, 2)
void attn_mma(const float* __restrict__ mask)
{
    extern __shared__ char smc[];
    __half* Ks = (__half*)smc;                 // 2 stages (also Q staging area)
    __half* Vs = Ks + 2 * KS_H;                // 2 stages
    const uint32_t ks_b = smem_u32(Ks);
    const uint32_t vs_b = smem_u32(Vs);

    const int tid = threadIdx.x, lane = tid & 31, w = tid >> 5;
    const int r0 = lane >> 2, c0 = lane & 3;
    const int g = lane >> 3, lr = lane & 7;
    const int q0 = blockIdx.x * 128;
    const int bh = blockIdx.y, b = bh >> 4, h = bh & 15;
    const int use_mask = g_maskflag;

    const int qAoff = (w * 32 + lr + (g & 1) * 8) * KSTH + (g >> 1) * 8;  // A-style Q
    const int kBoff = (lr + (g >> 1) * 8) * KSTH + (g & 1) * 8;           // B-style K
    const int vBoff = (lr + (g & 1) * 8) * KSTH + (g >> 1) * 8;           // trans-B V

    const __half* Kg0 = g_K + (size_t)bh * SS * HD;
    const __half* Vg0 = g_V + (size_t)bh * SS * HD;

    // stage Q tile (128 x 64 halves) into Ks area, pull A-frags
    const __half* Qg = g_Q + ((size_t)bh * SS + q0) * HD;
#pragma unroll
    for (int i = 0; i < 8; i++) {
        int c = tid + 128 * i;
        int row = c >> 3, c8 = c & 7;
        *(uint4*)(Ks + row * KSTH + c8 * 8) = *(const uint4*)(Qg + (size_t)row * HD + c8 * 8);
    }
    __syncthreads();
    uint32_t qf[2][4][4];
#pragma unroll
    for (int mt = 0; mt < 2; mt++)
#pragma unroll
        for (int kc = 0; kc < 4; kc++)
            ldsm_x4(qf[mt][kc], ks_b + (uint32_t)(qAoff + mt * 16 * KSTH + kc * 16) * 2);
    __syncthreads();   // Q reads done before K/V loads overwrite

    float o[2][8][4];
#pragma unroll
    for (int mt = 0; mt < 2; mt++)
#pragma unroll
        for (int nt = 0; nt < 8; nt++)
#pragma unroll
            for (int j = 0; j < 4; j++) o[mt][nt][j] = 0.f;
    float mrow[2][2], lrow[2][2];
#pragma unroll
    for (int mt = 0; mt < 2; mt++) { mrow[mt][0] = mrow[mt][1] = -INFINITY;
                                     lrow[mt][0] = lrow[mt][1] = 0.f; }

    auto load_kv = [&](int t, int s) {
#pragma unroll
        for (int i = 0; i < 4; i++) {
            int c = tid + 128 * i;               // 0..511
            int row = c >> 3, c8 = c & 7;
            cp16(ks_b + (uint32_t)(s * KS_H + row * KSTH + c8 * 8) * 2,
                 Kg0 + (size_t)(t * 64 + row) * HD + c8 * 8);
            cp16(vs_b + (uint32_t)(s * KS_H + row * KSTH + c8 * 8) * 2,
                 Vg0 + (size_t)(t * 64 + row) * HD + c8 * 8);
        }
    };

    load_kv(0, 0); CP_COMMIT();

    const int NIT = SS / 64;                     // 32
    for (int it = 0; it < NIT; it++) {
        if (it + 1 < NIT) load_kv(it + 1, (it + 1) & 1);
        CP_COMMIT();
        asm volatile("cp.async.wait_group 1;" ::: "memory");
        __syncthreads();

        const uint32_t ksb = ks_b + (uint32_t)((it & 1) * KS_H) * 2;
        const uint32_t vsb = vs_b + (uint32_t)((it & 1) * KS_H) * 2;

        // ---- S = Q @ K^T (per warp: 32 x 64), pipelined K ldsm ----
        float s[2][8][4];
#pragma unroll
        for (int mt = 0; mt < 2; mt++)
#pragma unroll
            for (int nt = 0; nt < 8; nt++)
#pragma unroll
                for (int j = 0; j < 4; j++) s[mt][nt][j] = 0.f;

        uint32_t kp[2][4];
        ldsm_x4(kp[0], ksb + (uint32_t)(kBoff) * 2);   // (kc=0, p=0)
#pragma unroll
        for (int idx = 0; idx < 16; idx++) {
            const int kc = idx >> 2, p = idx & 3;
            if (idx + 1 < 16) {
                const int nkc = (idx + 1) >> 2, np = (idx + 1) & 3;
                ldsm_x4(kp[(idx + 1) & 1],
                        ksb + (uint32_t)(kBoff + np * 16 * KSTH + nkc * 16) * 2);
            }
            const uint32_t* kk = kp[idx & 1];
            const uint32_t f0[2] = { kk[0], kk[1] };
            const uint32_t f1[2] = { kk[2], kk[3] };
            mma_f16(s[0][2 * p],     qf[0][kc], f0);
            mma_f16(s[1][2 * p],     qf[1][kc], f0);
            mma_f16(s[0][2 * p + 1], qf[0][kc], f1);
            mma_f16(s[1][2 * p + 1], qf[1][kc], f1);
        }

        if (use_mask) {
#pragma unroll
            for (int mt = 0; mt < 2; mt++) {
                const float* Mg = mask + ((size_t)b * SS + (q0 + w * 32 + mt * 16 + r0)) * SS
                                       + it * 64;
#pragma unroll
                for (int nt = 0; nt < 8; nt++) {
                    float2 mlo = *(const float2*)(Mg + nt * 8 + 2 * c0);
                    float2 mhi = *(const float2*)(Mg + (size_t)8 * SS + nt * 8 + 2 * c0);
                    s[mt][nt][0] = fmaf(mlo.x, LOG2E, s[mt][nt][0]);
                    s[mt][nt][1] = fmaf(mlo.y, LOG2E, s[mt][nt][1]);
                    s[mt][nt][2] = fmaf(mhi.x, LOG2E, s[mt][nt][2]);
                    s[mt][nt][3] = fmaf(mhi.y, LOG2E, s[mt][nt][3]);
                }
            }
        }

        // ---- online softmax (base-2); P packed into A-frags in registers ----
        uint32_t pf[2][4][4];                    // [mt][kc][frag]
#pragma unroll
        for (int mt = 0; mt < 2; mt++) {
            float mx_lo = -INFINITY, mx_hi = -INFINITY;
#pragma unroll
            for (int nt = 0; nt < 8; nt++) {
                mx_lo = fmaxf(mx_lo, fmaxf(s[mt][nt][0], s[mt][nt][1]));
                mx_hi = fmaxf(mx_hi, fmaxf(s[mt][nt][2], s[mt][nt][3]));
            }
            mx_lo = fmaxf(mx_lo, __shfl_xor_sync(0xffffffffu, mx_lo, 1));
            mx_lo = fmaxf(mx_lo, __shfl_xor_sync(0xffffffffu, mx_lo, 2));
            mx_hi = fmaxf(mx_hi, __shfl_xor_sync(0xffffffffu, mx_hi, 1));
            mx_hi = fmaxf(mx_hi, __shfl_xor_sync(0xffffffffu, mx_hi, 2));
            const float nm_lo = fmaxf(mrow[mt][0], mx_lo);
            const float nm_hi = fmaxf(mrow[mt][1], mx_hi);
            const float corr_lo = exp2f(mrow[mt][0] - nm_lo);
            const float corr_hi = exp2f(mrow[mt][1] - nm_hi);
            mrow[mt][0] = nm_lo; mrow[mt][1] = nm_hi;

            float sum_lo = 0.f, sum_hi = 0.f;
#pragma unroll
            for (int nt = 0; nt < 8; nt++) {
                float p0 = exp2f(s[mt][nt][0] - nm_lo);
                float p1 = exp2f(s[mt][nt][1] - nm_lo);
                float p2 = exp2f(s[mt][nt][2] - nm_hi);
                float p3 = exp2f(s[mt][nt][3] - nm_hi);
                sum_lo += p0 + p1; sum_hi += p2 + p3;
                // C-frag -> A-frag: kc = nt>>1; even nt -> frags 0,1; odd -> 2,3
                const int kc = nt >> 1, base = (nt & 1) * 2;
                pf[mt][kc][base + 0] = pack_h2(p0, p1);
                pf[mt][kc][base + 1] = pack_h2(p2, p3);
            }
            sum_lo += __shfl_xor_sync(0xffffffffu, sum_lo, 1);
            sum_lo += __shfl_xor_sync(0xffffffffu, sum_lo, 2);
            sum_hi += __shfl_xor_sync(0xffffffffu, sum_hi, 1);
            sum_hi += __shfl_xor_sync(0xffffffffu, sum_hi, 2);
            lrow[mt][0] = lrow[mt][0] * corr_lo + sum_lo;
            lrow[mt][1] = lrow[mt][1] * corr_hi + sum_hi;
#pragma unroll
            for (int nt = 0; nt < 8; nt++) {
                o[mt][nt][0] *= corr_lo; o[mt][nt][1] *= corr_lo;
                o[mt][nt][2] *= corr_hi; o[mt][nt][3] *= corr_hi;
            }
        }

        // ---- O += P @ V (per warp: 32 x 64, k=64), pipelined V ldsm ----
        uint32_t vp[2][4];
        ldsm_x4_t(vp[0], vsb + (uint32_t)(vBoff) * 2);   // (kc=0, dp=0)
#pragma unroll
        for (int idx = 0; idx < 16; idx++) {
            const int kc = idx >> 2, dp = idx & 3;
            if (idx + 1 < 16) {
                const int nkc = (idx + 1) >> 2, ndp = (idx + 1) & 3;
                ldsm_x4_t(vp[(idx + 1) & 1],
                          vsb + (uint32_t)(vBoff + nkc * 16 * KSTH + ndp * 16) * 2);
            }
            const uint32_t* vv = vp[idx & 1];
            const uint32_t f0[2] = { vv[0], vv[1] };
            const uint32_t f1[2] = { vv[2], vv[3] };
            mma_f16(o[0][2 * dp],     pf[0][kc], f0);
            mma_f16(o[1][2 * dp],     pf[1][kc], f0);
            mma_f16(o[0][2 * dp + 1], pf[0][kc], f1);
            mma_f16(o[1][2 * dp + 1], pf[1][kc], f1);
        }
        __syncthreads();   // all warps done with this K/V stage before reload
    }

    // epilogue: normalize, write fp16 Z[b*SS+q][h*HD+d]
#pragma unroll
    for (int mt = 0; mt < 2; mt++) {
        const float inv_lo = 1.f / lrow[mt][0], inv_hi = 1.f / lrow[mt][1];
        const int qlo = q0 + w * 32 + mt * 16 + r0;
        __half* Zlo = g_Z + ((size_t)b * SS + qlo) * DIM + h * HD;
        __half* Zhi = Zlo + (size_t)8 * DIM;
#pragma unroll
        for (int nt = 0; nt < 8; nt++) {
            const int d = nt * 8 + 2 * c0;
            *(__half2*)(Zlo + d) =
                __float22half2_rn(make_float2(o[mt][nt][0] * inv_lo, o[mt][nt][1] * inv_lo));
            *(__half2*)(Zhi + d) =
                __float22half2_rn(make_float2(o[mt][nt][2] * inv_hi, o[mt][nt][3] * inv_hi));
        }
    }
}

// ---------------------------------------------------------------------------
extern "C" void kernel_launch(void* const* d_in, const int* in_sizes, int n_in,
                              void* d_out, int out_size)
{
    const float* q    = (const float*)d_in[0];
    const float* k    = (const float*)d_in[1];
    const float* v    = (const float*)d_in[2];
    const float* mask = (const float*)d_in[3];
    const float* Wq   = (const float*)d_in[4];
    const float* Wk   = (const float*)d_in[5];
    const float* Wv   = (const float*)d_in[6];
    const float* Wd   = (const float*)d_in[7];

    cudaFuncSetAttribute(qkv_gemm, cudaFuncAttributeMaxDynamicSharedMemorySize, GEMM_SMEM);
    cudaFuncSetAttribute(out_gemm, cudaFuncAttributeMaxDynamicSharedMemorySize, GEMM_SMEM);
    cudaFuncSetAttribute(attn_mma, cudaFuncAttributeMaxDynamicSharedMemorySize, ATTN_SMEM);

    // launch 1: f32->fp16 convert everything + mask scan
    round_all<<<dim3(2048, 1, 8), 256>>>(q, k, v, Wq, Wk, Wv, Wd, mask);

    // launch 2: q/k/v projections (fp16 mma; Q pre-scaled by 0.125*log2e)
    qkv_gemm<<<dim3(MROWS/128, DIM/128, 3), 128, GEMM_SMEM>>>();

    // launch 3: flash attention (fp16 mma, base-2 softmax, P in registers)
    attn_mma<<<dim3(SS/128, BB*NH), 128, ATTN_SMEM>>>(mask);

    // launch 4: output projection, f32 out (+ maskflag reset)
    out_gemm<<<dim3(MROWS/128, DIM/128), 128, GEMM_SMEM>>>((float*)d_out);
}